// round 2
// baseline (speedup 1.0000x reference)
#include <cuda_runtime.h>

#define NB 32
#define NN 1024
#define NF 64

// Scratch (no runtime allocation allowed)
__device__ float g_Y[NB*NN*NF];      // att_X = X @ att_W
__device__ float g_P[NB*NN*NF];      // XW    = X @ W
__device__ float g_base[NB*NN*NF];   // X @ self_W + bias
__device__ float g_s[NF];            // a.sum(0)

// ---------------------------------------------------------------------------
// s[j] = sum_i a[i][j]
__global__ void scale_kernel(const float* __restrict__ a) {
    int j = threadIdx.x;
    float s = 0.f;
    #pragma unroll
    for (int i = 0; i < NF; i++) s += a[i*NF + j];
    g_s[j] = s;
}

// ---------------------------------------------------------------------------
// prep: Y = X@attW ; P = X@W ; base = X@selfW + bias
// grid 256 CTAs (128 rows each), 256 threads
__global__ void __launch_bounds__(256, 1)
prep_kernel(const float* __restrict__ X,
            const float* __restrict__ W,
            const float* __restrict__ attW,
            const float* __restrict__ selfW,
            const float* __restrict__ bias) {
    extern __shared__ float sm[];
    float* XT = sm;              // [64][132]  X tile transposed
    float* WA = XT + 64*132;     // [64][68]
    float* WW = WA + 64*68;      // [64][68]
    float* WS = WW + 64*68;      // [64][68]
    float* BS = WS + 64*68;      // [64]
    int tid = threadIdx.x;
    int row0 = blockIdx.x * 128;

    const float4* X4 = (const float4*)(X + (size_t)row0*NF);
    #pragma unroll
    for (int q = 0; q < 8; q++) {
        int idx = tid + q*256;           // 0..2047
        int r  = idx >> 4;               // row 0..127
        int c4 = (idx & 15) << 2;        // feature 0..60
        float4 v = X4[idx];
        XT[(c4+0)*132 + r] = v.x;
        XT[(c4+1)*132 + r] = v.y;
        XT[(c4+2)*132 + r] = v.z;
        XT[(c4+3)*132 + r] = v.w;
    }
    const float4* A4 = (const float4*)attW;
    const float4* W4 = (const float4*)W;
    const float4* S4 = (const float4*)selfW;
    #pragma unroll
    for (int q = 0; q < 4; q++) {
        int idx = tid + q*256;           // 0..1023
        int r  = idx >> 4;
        int c4 = (idx & 15) << 2;
        *(float4*)&WA[r*68 + c4] = A4[idx];
        *(float4*)&WW[r*68 + c4] = W4[idx];
        *(float4*)&WS[r*68 + c4] = S4[idx];
    }
    if (tid < 64) BS[tid] = bias[tid];
    __syncthreads();

    int tx = tid & 15, ty = tid >> 4;
    float accY[8][4], accP[8][4], accB[8][4];
    #pragma unroll
    for (int r = 0; r < 8; r++)
        #pragma unroll
        for (int c = 0; c < 4; c++) { accY[r][c]=0.f; accP[r][c]=0.f; accB[r][c]=0.f; }

    #pragma unroll 4
    for (int k = 0; k < 64; k++) {
        float a[8];
        float4 a0 = *(const float4*)&XT[k*132 + ty*8];
        float4 a1 = *(const float4*)&XT[k*132 + ty*8 + 4];
        a[0]=a0.x; a[1]=a0.y; a[2]=a0.z; a[3]=a0.w;
        a[4]=a1.x; a[5]=a1.y; a[6]=a1.z; a[7]=a1.w;
        float4 wa = *(const float4*)&WA[k*68 + tx*4];
        float4 ww = *(const float4*)&WW[k*68 + tx*4];
        float4 ws = *(const float4*)&WS[k*68 + tx*4];
        #pragma unroll
        for (int r = 0; r < 8; r++) {
            accY[r][0] += a[r]*wa.x; accY[r][1] += a[r]*wa.y;
            accY[r][2] += a[r]*wa.z; accY[r][3] += a[r]*wa.w;
            accP[r][0] += a[r]*ww.x; accP[r][1] += a[r]*ww.y;
            accP[r][2] += a[r]*ww.z; accP[r][3] += a[r]*ww.w;
            accB[r][0] += a[r]*ws.x; accB[r][1] += a[r]*ws.y;
            accB[r][2] += a[r]*ws.z; accB[r][3] += a[r]*ws.w;
        }
    }

    float b0 = BS[tx*4+0], b1 = BS[tx*4+1], b2 = BS[tx*4+2], b3 = BS[tx*4+3];
    #pragma unroll
    for (int r = 0; r < 8; r++) {
        size_t row = (size_t)row0 + ty*8 + r;
        *(float4*)&g_Y[row*NF + tx*4] =
            make_float4(accY[r][0], accY[r][1], accY[r][2], accY[r][3]);
        *(float4*)&g_P[row*NF + tx*4] =
            make_float4(accP[r][0], accP[r][1], accP[r][2], accP[r][3]);
        *(float4*)&g_base[row*NF + tx*4] =
            make_float4(accB[r][0]+b0, accB[r][1]+b1, accB[r][2]+b2, accB[r][3]+b3);
    }
}

// ---------------------------------------------------------------------------
// Fused main kernel: per (batch b, 128-row tile bx):
//   O = leaky(mask(Yi_s @ Yk^T)) @ Pk  accumulated over 16 k-tiles of 64 rows
//   out = O + base
// grid (8, 32), 256 threads, occupancy 2 (smem ~101KB, regs <=128)
__global__ void __launch_bounds__(256, 2)
main_kernel(float* __restrict__ out) {
    extern __shared__ float sm[];
    float* TA  = sm;                 // [64][132]  Yi^T * s   (feature-major)
    float* TB  = TA + 64*132;        // [64][68]   Yk^T       (feature-major)
    float* PS  = TB + 64*68;         // [64][68]   Pk row-major
    float* SSm = PS + 64*68;         // [128][68]  S tile (post-activation)
    float* sc  = SSm + 128*68;       // [64]

    int tid = threadIdx.x;
    int tx = tid & 15, ty = tid >> 4;
    int bx = blockIdx.x;             // row tile (128 rows)
    int b  = blockIdx.y;             // batch
    const float* Yb = g_Y    + (size_t)b*NN*NF;
    const float* Pb = g_P    + (size_t)b*NN*NF;
    const float* Bb = g_base + (size_t)b*NN*NF;
    float*       Ob = out    + (size_t)b*NN*NF;

    if (tid < 64) sc[tid] = g_s[tid];
    __syncthreads();

    // Load Yi tile transposed, scaled by s[feature]
    {
        const float4* Y4 = (const float4*)(Yb + (size_t)bx*128*NF);
        #pragma unroll
        for (int q = 0; q < 8; q++) {
            int idx = tid + q*256;       // 0..2047
            int r  = idx >> 4;           // 0..127
            int c4 = (idx & 15) << 2;
            float4 v = Y4[idx];
            TA[(c4+0)*132 + r] = v.x * sc[c4+0];
            TA[(c4+1)*132 + r] = v.y * sc[c4+1];
            TA[(c4+2)*132 + r] = v.z * sc[c4+2];
            TA[(c4+3)*132 + r] = v.w * sc[c4+3];
        }
    }

    float O[8][4];
    #pragma unroll
    for (int r = 0; r < 8; r++)
        #pragma unroll
        for (int c = 0; c < 4; c++) O[r][c] = 0.f;

    int ig0 = bx*128 + ty*8;             // global row base for this thread

    for (int kt = 0; kt < 16; kt++) {
        __syncthreads();                 // prior GEMM2 done with TB/PS/SSm
        // Load Yk tile (transposed) and Pk tile (row-major): 64 rows x 64
        {
            const float4* Yk4 = (const float4*)(Yb + (size_t)kt*64*NF);
            const float4* Pk4 = (const float4*)(Pb + (size_t)kt*64*NF);
            #pragma unroll
            for (int q = 0; q < 4; q++) {
                int idx = tid + q*256;   // 0..1023
                int r  = idx >> 4;       // 0..63
                int c4 = (idx & 15) << 2;
                float4 v = Yk4[idx];
                TB[(c4+0)*68 + r] = v.x;
                TB[(c4+1)*68 + r] = v.y;
                TB[(c4+2)*68 + r] = v.z;
                TB[(c4+3)*68 + r] = v.w;
                *(float4*)&PS[r*68 + c4] = Pk4[idx];
            }
        }
        __syncthreads();

        // GEMM1: S[8][4] = (Yi_s) @ Yk^T  micro-tile
        //   rows: ty*8 + r  (contiguous), cols: tx + 16*c (strided)
        float S[8][4];
        #pragma unroll
        for (int r = 0; r < 8; r++)
            #pragma unroll
            for (int c = 0; c < 4; c++) S[r][c] = 0.f;

        #pragma unroll 8
        for (int k = 0; k < 64; k++) {
            float a[8], bf[4];
            float4 a0 = *(const float4*)&TA[k*132 + ty*8];
            float4 a1 = *(const float4*)&TA[k*132 + ty*8 + 4];
            a[0]=a0.x; a[1]=a0.y; a[2]=a0.z; a[3]=a0.w;
            a[4]=a1.x; a[5]=a1.y; a[6]=a1.z; a[7]=a1.w;
            #pragma unroll
            for (int c = 0; c < 4; c++) bf[c] = TB[k*68 + tx + 16*c];
            #pragma unroll
            for (int r = 0; r < 8; r++)
                #pragma unroll
                for (int c = 0; c < 4; c++)
                    S[r][c] += a[r]*bf[c];
        }

        // mask diagonal + leaky_relu(0.01), store S to smem
        int kg0 = kt*64 + tx;
        #pragma unroll
        for (int r = 0; r < 8; r++) {
            int ig = ig0 + r;
            #pragma unroll
            for (int c = 0; c < 4; c++) {
                float v = S[r][c];
                v = (v > 0.f) ? v : 0.01f*v;
                if (ig == kg0 + 16*c) v = 0.f;
                SSm[(ty*8+r)*68 + tx + 16*c] = v;
            }
        }
        __syncthreads();

        // GEMM2: O += S @ Pk   (rows ty*8+r, output cols tx*4..+3)
        #pragma unroll 4
        for (int kk = 0; kk < 64; kk++) {
            float4 p = *(const float4*)&PS[kk*68 + tx*4];
            #pragma unroll
            for (int r = 0; r < 8; r++) {
                float s = SSm[(ty*8+r)*68 + kk];
                O[r][0] += s*p.x; O[r][1] += s*p.y;
                O[r][2] += s*p.z; O[r][3] += s*p.w;
            }
        }
    }

    // epilogue: add base (X@selfW + bias), write out
    #pragma unroll
    for (int r = 0; r < 8; r++) {
        size_t row = (size_t)bx*128 + ty*8 + r;
        float4 bb = *(const float4*)&Bb[row*NF + tx*4];
        float4 o  = make_float4(O[r][0]+bb.x, O[r][1]+bb.y,
                                O[r][2]+bb.z, O[r][3]+bb.w);
        *(float4*)&Ob[row*NF + tx*4] = o;
    }
}

// ---------------------------------------------------------------------------
extern "C" void kernel_launch(void* const* d_in, const int* in_sizes, int n_in,
                              void* d_out, int out_size) {
    const float* X     = (const float*)d_in[0];
    // d_in[1] = A  (unused in forward)
    const float* W     = (const float*)d_in[2];
    const float* attW  = (const float*)d_in[3];
    const float* amat  = (const float*)d_in[4];
    const float* bias  = (const float*)d_in[5];
    const float* selfW = (const float*)d_in[6];
    float* out = (float*)d_out;

    size_t smem1 = (size_t)(64*132 + 3*64*68 + 64) * sizeof(float);   // 86 KB
    size_t smem2 = (size_t)(64*132 + 64*68 + 64*68 + 128*68 + 64)
                   * sizeof(float);                                    // ~101 KB
    cudaFuncSetAttribute((const void*)prep_kernel,
                         cudaFuncAttributeMaxDynamicSharedMemorySize, (int)smem1);
    cudaFuncSetAttribute((const void*)main_kernel,
                         cudaFuncAttributeMaxDynamicSharedMemorySize, (int)smem2);

    scale_kernel<<<1, 64>>>(amat);
    prep_kernel<<<NB*NN/128, 256, smem1>>>(X, W, attW, selfW, bias);
    dim3 g2(NN/128, NB);
    main_kernel<<<g2, 256, smem2>>>(out);
}

// round 4
// speedup vs baseline: 1.9695x; 1.9695x over previous
#include <cuda_runtime.h>
#include <cuda_bf16.h>
#include <cstdint>

#define NB 32
#define NN 1024
#define NF 64

// ---------------------------------------------------------------------------
// Device scratch (no runtime allocation allowed)
__device__ __align__(16) float g_Y[NB*NN*NF];            // att_X fp32
__device__ __align__(16) float g_base[NB*NN*NF];         // X@self_W + bias
__device__ __align__(16) float g_s[NF];                  // a.sum(0)
__device__ __align__(16) unsigned short g_Yh[NB*NN*NF];  // bf16 hi of att_X [b][n][f]
__device__ __align__(16) unsigned short g_Yl[NB*NN*NF];  // bf16 lo
__device__ __align__(16) unsigned short g_PTh[NB*NF*NN]; // bf16 hi of (XW)^T [b][g][n]
__device__ __align__(16) unsigned short g_PTl[NB*NF*NN]; // bf16 lo

// ---------------------------------------------------------------------------
#define SWZ(o) ((o) ^ (((o) >> 3) & 0x70))

__device__ __forceinline__ uint32_t smem_u32(const void* p) {
    uint32_t a;
    asm("{ .reg .u64 t; cvta.to.shared.u64 t, %1; cvt.u32.u64 %0, t; }"
        : "=r"(a) : "l"(p));
    return a;
}

#define LDSM4(r0, r1, r2, r3, addr) \
    asm volatile("ldmatrix.sync.aligned.m8n8.x4.shared.b16 {%0,%1,%2,%3}, [%4];" \
                 : "=r"(r0), "=r"(r1), "=r"(r2), "=r"(r3) : "r"(addr))

__device__ __forceinline__ void mma16816(float* d, const uint32_t* a,
                                         const uint32_t* b) {
    asm volatile(
        "mma.sync.aligned.m16n8k16.row.col.f32.bf16.bf16.f32 "
        "{%0,%1,%2,%3}, {%4,%5,%6,%7}, {%8,%9}, {%0,%1,%2,%3};"
        : "+f"(d[0]), "+f"(d[1]), "+f"(d[2]), "+f"(d[3])
        : "r"(a[0]), "r"(a[1]), "r"(a[2]), "r"(a[3]), "r"(b[0]), "r"(b[1]));
}

__device__ __forceinline__ void split2(float a, unsigned short& h, unsigned short& l) {
    __nv_bfloat16 hb = __float2bfloat16(a);
    float r = a - __bfloat162float(hb);
    __nv_bfloat16 lb = __float2bfloat16(r);
    h = __bfloat16_as_ushort(hb);
    l = __bfloat16_as_ushort(lb);
}

// ---------------------------------------------------------------------------
// s[j] = sum_i a[i][j]
__global__ void scale_kernel(const float* __restrict__ a) {
    int j = threadIdx.x;
    float s = 0.f;
    #pragma unroll
    for (int i = 0; i < NF; i++) s += a[i*NF + j];
    g_s[j] = s;
}

// ---------------------------------------------------------------------------
// prep: Y = X@attW (fp32 + bf16 hi/lo); PT = (X@W)^T (bf16 hi/lo); base = X@selfW + bias
__global__ void __launch_bounds__(256, 1)
prep_kernel(const float* __restrict__ X,
            const float* __restrict__ W,
            const float* __restrict__ attW,
            const float* __restrict__ selfW,
            const float* __restrict__ bias) {
    extern __shared__ float sm[];
    float* XT = sm;              // [64][132]
    float* WA = XT + 64*132;
    float* WW = WA + 64*68;
    float* WS = WW + 64*68;
    float* BS = WS + 64*68;
    int tid = threadIdx.x;
    int row0 = blockIdx.x * 128;

    const float4* X4 = (const float4*)(X + (size_t)row0*NF);
    #pragma unroll
    for (int q = 0; q < 8; q++) {
        int idx = tid + q*256;
        int r  = idx >> 4;
        int c4 = (idx & 15) << 2;
        float4 v = X4[idx];
        XT[(c4+0)*132 + r] = v.x;
        XT[(c4+1)*132 + r] = v.y;
        XT[(c4+2)*132 + r] = v.z;
        XT[(c4+3)*132 + r] = v.w;
    }
    const float4* A4 = (const float4*)attW;
    const float4* W4 = (const float4*)W;
    const float4* S4 = (const float4*)selfW;
    #pragma unroll
    for (int q = 0; q < 4; q++) {
        int idx = tid + q*256;
        int r  = idx >> 4;
        int c4 = (idx & 15) << 2;
        *(float4*)&WA[r*68 + c4] = A4[idx];
        *(float4*)&WW[r*68 + c4] = W4[idx];
        *(float4*)&WS[r*68 + c4] = S4[idx];
    }
    if (tid < 64) BS[tid] = bias[tid];
    __syncthreads();

    int tx = tid & 15, ty = tid >> 4;
    float accY[8][4], accP[8][4], accB[8][4];
    #pragma unroll
    for (int r = 0; r < 8; r++)
        #pragma unroll
        for (int c = 0; c < 4; c++) { accY[r][c]=0.f; accP[r][c]=0.f; accB[r][c]=0.f; }

    #pragma unroll 4
    for (int k = 0; k < 64; k++) {
        float a[8];
        float4 a0 = *(const float4*)&XT[k*132 + ty*8];
        float4 a1 = *(const float4*)&XT[k*132 + ty*8 + 4];
        a[0]=a0.x; a[1]=a0.y; a[2]=a0.z; a[3]=a0.w;
        a[4]=a1.x; a[5]=a1.y; a[6]=a1.z; a[7]=a1.w;
        float4 wa = *(const float4*)&WA[k*68 + tx*4];
        float4 ww = *(const float4*)&WW[k*68 + tx*4];
        float4 ws = *(const float4*)&WS[k*68 + tx*4];
        #pragma unroll
        for (int r = 0; r < 8; r++) {
            accY[r][0] += a[r]*wa.x; accY[r][1] += a[r]*wa.y;
            accY[r][2] += a[r]*wa.z; accY[r][3] += a[r]*wa.w;
            accP[r][0] += a[r]*ww.x; accP[r][1] += a[r]*ww.y;
            accP[r][2] += a[r]*ww.z; accP[r][3] += a[r]*ww.w;
            accB[r][0] += a[r]*ws.x; accB[r][1] += a[r]*ws.y;
            accB[r][2] += a[r]*ws.z; accB[r][3] += a[r]*ws.w;
        }
    }

    float b0 = BS[tx*4+0], b1 = BS[tx*4+1], b2 = BS[tx*4+2], b3 = BS[tx*4+3];
    #pragma unroll
    for (int r = 0; r < 8; r++) {
        size_t row = (size_t)row0 + ty*8 + r;
        *(float4*)&g_Y[row*NF + tx*4] =
            make_float4(accY[r][0], accY[r][1], accY[r][2], accY[r][3]);
        *(float4*)&g_base[row*NF + tx*4] =
            make_float4(accB[r][0]+b0, accB[r][1]+b1, accB[r][2]+b2, accB[r][3]+b3);
        unsigned short h[4], l[4];
        #pragma unroll
        for (int c = 0; c < 4; c++) split2(accY[r][c], h[c], l[c]);
        *(uint2*)&g_Yh[row*NF + tx*4] =
            make_uint2((uint32_t)h[0] | ((uint32_t)h[1]<<16),
                       (uint32_t)h[2] | ((uint32_t)h[3]<<16));
        *(uint2*)&g_Yl[row*NF + tx*4] =
            make_uint2((uint32_t)l[0] | ((uint32_t)l[1]<<16),
                       (uint32_t)l[2] | ((uint32_t)l[3]<<16));
    }

    // stage accP, write transposed bf16 hi/lo (XW)^T: PT[b][g][n]
    __syncthreads();
    float* Pst = sm;  // reuse: 128 x 65 floats
    #pragma unroll
    for (int r = 0; r < 8; r++)
        #pragma unroll
        for (int c = 0; c < 4; c++)
            Pst[(ty*8+r)*65 + tx*4+c] = accP[r][c];
    __syncthreads();

    int g = tid >> 2, q = tid & 3;
    int b_ = row0 >> 10;
    int n0 = row0 & 1023;
    size_t baseT = ((size_t)b_*NF + g)*NN + n0 + q*32;
    #pragma unroll
    for (int i = 0; i < 32; i += 4) {
        unsigned short h[4], l[4];
        #pragma unroll
        for (int j = 0; j < 4; j++)
            split2(Pst[(q*32 + i + j)*65 + g], h[j], l[j]);
        *(uint2*)&g_PTh[baseT + i] =
            make_uint2((uint32_t)h[0] | ((uint32_t)h[1]<<16),
                       (uint32_t)h[2] | ((uint32_t)h[3]<<16));
        *(uint2*)&g_PTl[baseT + i] =
            make_uint2((uint32_t)l[0] | ((uint32_t)l[1]<<16),
                       (uint32_t)l[2] | ((uint32_t)l[3]<<16));
    }
}

// ---------------------------------------------------------------------------
// Main kernel: warp-level bf16 mma.sync with 3-term split.
// Per CTA (batch b, 128-row tile bx); 8 warps in 4(m) x 2(n) grid.
// smem byte offsets (all tiles: rows of 128B, SW128-swizzled)
#define SA_H 0
#define SA_L 16384
#define SB_H 32768
#define SB_L 40960
#define SP_H 49152
#define SP_L 57344
#define SS_H 65536
#define SS_L 81920
#define SM_TOT 98304

// one GEMM stage: acc += 3-term split product of A[128x64] x B[64x64]^T tile
__device__ __forceinline__ void gemm_tile(uint32_t sb, uint32_t aH, uint32_t aL,
                                          uint32_t bH, uint32_t bL,
                                          int wm, int wn, int lane,
                                          float acc[2][4][4]) {
    int lr = lane & 15, lh = lane >> 4;
    #pragma unroll
    for (int kc = 0; kc < 4; kc++) {
        uint32_t colb = kc*32 + lh*16;
        uint32_t ah[2][4], al[2][4], bh[4][2], bl[4][2];
        #pragma unroll
        for (int mi = 0; mi < 2; mi++) {
            uint32_t off = (uint32_t)(wm*32 + mi*16 + lr)*128 + colb;
            LDSM4(ah[mi][0], ah[mi][1], ah[mi][2], ah[mi][3], sb + aH + SWZ(off));
            LDSM4(al[mi][0], al[mi][1], al[mi][2], al[mi][3], sb + aL + SWZ(off));
        }
        #pragma unroll
        for (int np = 0; np < 2; np++) {
            uint32_t off = (uint32_t)(wn*32 + np*16 + lr)*128 + colb;
            uint32_t r0, r1, r2, r3;
            LDSM4(r0, r1, r2, r3, sb + bH + SWZ(off));
            bh[np*2][0]=r0; bh[np*2][1]=r2; bh[np*2+1][0]=r1; bh[np*2+1][1]=r3;
            LDSM4(r0, r1, r2, r3, sb + bL + SWZ(off));
            bl[np*2][0]=r0; bl[np*2][1]=r2; bl[np*2+1][0]=r1; bl[np*2+1][1]=r3;
        }
        #pragma unroll
        for (int mi = 0; mi < 2; mi++)
            #pragma unroll
            for (int ni = 0; ni < 4; ni++) {
                mma16816(acc[mi][ni], ah[mi], bh[ni]);
                mma16816(acc[mi][ni], ah[mi], bl[ni]);
                mma16816(acc[mi][ni], al[mi], bh[ni]);
            }
    }
}

__global__ void __launch_bounds__(256, 2)
main_kernel(float* __restrict__ out) {
    extern __shared__ char smem[];
    uint32_t sb = smem_u32(smem);
    int tid = threadIdx.x, wid = tid >> 5, lane = tid & 31;
    int wm = wid >> 1, wn = wid & 1;
    int bx = blockIdx.x, b = blockIdx.y;

    // Build A = (Yi * s) split to SA_H/SA_L (128 rows x 64 bf16, swizzled)
    {
        int r = tid >> 1, hf = tid & 1;
        size_t yr = ((size_t)(b*NN + bx*128 + r))*NF + hf*32;
        const float4* Y4  = (const float4*)(g_Y + yr);
        const float4* S4g = (const float4*)(g_s + hf*32);
        uint32_t rb = (uint32_t)r*128 + hf*64;
        #pragma unroll
        for (int f4 = 0; f4 < 8; f4++) {
            float4 v = Y4[f4];
            float4 s = S4g[f4];
            unsigned short h0,h1,h2,h3,l0,l1,l2,l3;
            split2(v.x*s.x, h0, l0); split2(v.y*s.y, h1, l1);
            split2(v.z*s.z, h2, l2); split2(v.w*s.w, h3, l3);
            uint32_t off = rb + f4*8;
            *(uint32_t*)(smem + SA_H + SWZ(off))   = (uint32_t)h0 | ((uint32_t)h1<<16);
            *(uint32_t*)(smem + SA_H + SWZ(off+4)) = (uint32_t)h2 | ((uint32_t)h3<<16);
            *(uint32_t*)(smem + SA_L + SWZ(off))   = (uint32_t)l0 | ((uint32_t)l1<<16);
            *(uint32_t*)(smem + SA_L + SWZ(off+4)) = (uint32_t)l2 | ((uint32_t)l3<<16);
        }
    }

    float oacc[2][4][4];
    #pragma unroll
    for (int mi = 0; mi < 2; mi++)
        #pragma unroll
        for (int ni = 0; ni < 4; ni++)
            #pragma unroll
            for (int d = 0; d < 4; d++) oacc[mi][ni][d] = 0.f;

    int lane4 = lane >> 2, lanec = (lane & 3) * 2;
    int tlr = tid >> 2, tsg = tid & 3;   // tile-load row/segment

    for (int kt = 0; kt < 16; kt++) {
        __syncthreads();  // A ready (iter 0); prior GEMM2 done with B/P (later)
        // Load B (Yk rows) and P ((XW)^T cols) tiles: 64x64 bf16 each, hi+lo
        {
            size_t yo = ((size_t)(b*NN + kt*64 + tlr))*NF + tsg*16;
            size_t po = ((size_t)(b*NF + tlr))*NN + kt*64 + tsg*16;
            uint32_t so = (uint32_t)tlr*128 + tsg*32;
            uint32_t s0 = SWZ(so), s1 = SWZ(so + 16);
            *(uint4*)(smem + SB_H + s0) = *(const uint4*)(g_Yh + yo);
            *(uint4*)(smem + SB_H + s1) = *(const uint4*)(g_Yh + yo + 8);
            *(uint4*)(smem + SB_L + s0) = *(const uint4*)(g_Yl + yo);
            *(uint4*)(smem + SB_L + s1) = *(const uint4*)(g_Yl + yo + 8);
            *(uint4*)(smem + SP_H + s0) = *(const uint4*)(g_PTh + po);
            *(uint4*)(smem + SP_H + s1) = *(const uint4*)(g_PTh + po + 8);
            *(uint4*)(smem + SP_L + s0) = *(const uint4*)(g_PTl + po);
            *(uint4*)(smem + SP_L + s1) = *(const uint4*)(g_PTl + po + 8);
        }
        __syncthreads();

        // GEMM1: S = A @ Yk^T (3-term)
        float sacc[2][4][4];
        #pragma unroll
        for (int mi = 0; mi < 2; mi++)
            #pragma unroll
            for (int ni = 0; ni < 4; ni++)
                #pragma unroll
                for (int d = 0; d < 4; d++) sacc[mi][ni][d] = 0.f;
        gemm_tile(sb, SA_H, SA_L, SB_H, SB_L, wm, wn, lane, sacc);

        // leaky + diag-mask + re-split -> SS_H/SS_L
        #pragma unroll
        for (int mi = 0; mi < 2; mi++)
            #pragma unroll
            for (int ni = 0; ni < 4; ni++) {
                int n = wn*32 + ni*8 + lanec;
                int jg = kt*64 + n;
                #pragma unroll
                for (int h = 0; h < 2; h++) {
                    int m = wm*32 + mi*16 + lane4 + h*8;
                    int ig = bx*128 + m;
                    float v0 = sacc[mi][ni][h*2];
                    float v1 = sacc[mi][ni][h*2+1];
                    v0 = (v0 > 0.f) ? v0 : 0.01f*v0;
                    v1 = (v1 > 0.f) ? v1 : 0.01f*v1;
                    if (ig == jg)     v0 = 0.f;
                    if (ig == jg + 1) v1 = 0.f;
                    unsigned short h0, h1, l0, l1;
                    split2(v0, h0, l0); split2(v1, h1, l1);
                    uint32_t off = (uint32_t)m*128 + n*2;
                    *(uint32_t*)(smem + SS_H + SWZ(off)) =
                        (uint32_t)h0 | ((uint32_t)h1<<16);
                    *(uint32_t*)(smem + SS_L + SWZ(off)) =
                        (uint32_t)l0 | ((uint32_t)l1<<16);
                }
            }
        __syncthreads();

        // GEMM2: O += S @ P (3-term)
        gemm_tile(sb, SS_H, SS_L, SP_H, SP_L, wm, wn, lane, oacc);
    }

    // Epilogue: out = O + base
    #pragma unroll
    for (int mi = 0; mi < 2; mi++)
        #pragma unroll
        for (int ni = 0; ni < 4; ni++) {
            int n = wn*32 + ni*8 + lanec;
            #pragma unroll
            for (int h = 0; h < 2; h++) {
                int m = wm*32 + mi*16 + lane4 + h*8;
                size_t gi = ((size_t)(b*NN + bx*128 + m))*NF + n;
                float2 bb = *(const float2*)(g_base + gi);
                float2 o = make_float2(oacc[mi][ni][h*2]   + bb.x,
                                       oacc[mi][ni][h*2+1] + bb.y);
                *(float2*)(out + gi) = o;
            }
        }
}

// ---------------------------------------------------------------------------
extern "C" void kernel_launch(void* const* d_in, const int* in_sizes, int n_in,
                              void* d_out, int out_size) {
    const float* X     = (const float*)d_in[0];
    // d_in[1] = A (unused in forward)
    const float* W     = (const float*)d_in[2];
    const float* attW  = (const float*)d_in[3];
    const float* amat  = (const float*)d_in[4];
    const float* bias  = (const float*)d_in[5];
    const float* selfW = (const float*)d_in[6];
    float* out = (float*)d_out;

    size_t smem1 = (size_t)(64*132 + 3*64*68 + 64) * sizeof(float);
    cudaFuncSetAttribute((const void*)prep_kernel,
                         cudaFuncAttributeMaxDynamicSharedMemorySize, (int)smem1);
    cudaFuncSetAttribute((const void*)main_kernel,
                         cudaFuncAttributeMaxDynamicSharedMemorySize, SM_TOT);

    scale_kernel<<<1, 64>>>(amat);
    prep_kernel<<<NB*NN/128, 256, smem1>>>(X, W, attW, selfW, bias);
    dim3 g2(NN/128, NB);
    main_kernel<<<g2, 256, SM_TOT>>>(out);
}

// round 6
// speedup vs baseline: 2.5879x; 1.3140x over previous
#include <cuda_runtime.h>
#include <cuda_fp16.h>
#include <cstdint>

#define NB 32
#define NN 1024
#define NF 64

// ---------------------------------------------------------------------------
// Device scratch (no runtime allocation allowed)
__device__ __align__(16) float g_base[NB*NN*NF];          // X@self_W + bias (fp32)
__device__ __align__(16) unsigned short g_Ah[NB*NN*NF];   // fp16 hi of (att_X * s) [b][n][f]
__device__ __align__(16) unsigned short g_Al[NB*NN*NF];   // fp16 lo
__device__ __align__(16) unsigned short g_Yh[NB*NN*NF];   // fp16 of att_X [b][n][f]
__device__ __align__(16) unsigned short g_PTh[NB*NF*NN];  // fp16 of (XW)^T [b][g][n]

// ---------------------------------------------------------------------------
#define SWZ(o) ((o) ^ (((o) >> 3) & 0x70))

__device__ __forceinline__ uint32_t smem_u32(const void* p) {
    uint32_t a;
    asm("{ .reg .u64 t; cvta.to.shared.u64 t, %1; cvt.u32.u64 %0, t; }"
        : "=r"(a) : "l"(p));
    return a;
}

#define LDSM4(r0, r1, r2, r3, addr) \
    asm volatile("ldmatrix.sync.aligned.m8n8.x4.shared.b16 {%0,%1,%2,%3}, [%4];" \
                 : "=r"(r0), "=r"(r1), "=r"(r2), "=r"(r3) : "r"(addr))

__device__ __forceinline__ void mma16816(float* d, const uint32_t* a,
                                         const uint32_t* b) {
    asm volatile(
        "mma.sync.aligned.m16n8k16.row.col.f32.f16.f16.f32 "
        "{%0,%1,%2,%3}, {%4,%5,%6,%7}, {%8,%9}, {%0,%1,%2,%3};"
        : "+f"(d[0]), "+f"(d[1]), "+f"(d[2]), "+f"(d[3])
        : "r"(a[0]), "r"(a[1]), "r"(a[2]), "r"(a[3]), "r"(b[0]), "r"(b[1]));
}

__device__ __forceinline__ void split2h(float a, unsigned short& h, unsigned short& l) {
    __half hh = __float2half_rn(a);
    float r = a - __half2float(hh);
    __half ll = __float2half_rn(r);
    h = __half_as_ushort(hh);
    l = __half_as_ushort(ll);
}
__device__ __forceinline__ unsigned short h16(float a) {
    return __half_as_ushort(__float2half_rn(a));
}

// ---------------------------------------------------------------------------
// prep: s = a.sum(0); Y = X@attW -> g_Yh (fp16), g_Ah/g_Al (fp16 split of Y*s);
//       PT = (X@W)^T -> g_PTh (fp16); base = X@selfW + bias (fp32)
__global__ void __launch_bounds__(256, 2)
prep_kernel(const float* __restrict__ X,
            const float* __restrict__ W,
            const float* __restrict__ attW,
            const float* __restrict__ selfW,
            const float* __restrict__ bias,
            const float* __restrict__ amat) {
    extern __shared__ float sm[];
    float* XT = sm;              // [64][132]
    float* WA = XT + 64*132;
    float* WW = WA + 64*68;
    float* WS = WW + 64*68;
    float* BS = WS + 64*68;      // [64] bias
    float* SC = BS + 64;         // [64] s
    int tid = threadIdx.x;
    int row0 = blockIdx.x * 128;

    // s[j] = sum_i amat[i][j] (threads 0..63)
    if (tid < 64) {
        float s = 0.f;
        #pragma unroll 8
        for (int i = 0; i < NF; i++) s += amat[i*NF + tid];
        SC[tid] = s;
    }

    const float4* X4 = (const float4*)(X + (size_t)row0*NF);
    #pragma unroll
    for (int q = 0; q < 8; q++) {
        int idx = tid + q*256;
        int r  = idx >> 4;
        int c4 = (idx & 15) << 2;
        float4 v = X4[idx];
        XT[(c4+0)*132 + r] = v.x;
        XT[(c4+1)*132 + r] = v.y;
        XT[(c4+2)*132 + r] = v.z;
        XT[(c4+3)*132 + r] = v.w;
    }
    const float4* A4 = (const float4*)attW;
    const float4* W4 = (const float4*)W;
    const float4* S4 = (const float4*)selfW;
    #pragma unroll
    for (int q = 0; q < 4; q++) {
        int idx = tid + q*256;
        int r  = idx >> 4;
        int c4 = (idx & 15) << 2;
        *(float4*)&WA[r*68 + c4] = A4[idx];
        *(float4*)&WW[r*68 + c4] = W4[idx];
        *(float4*)&WS[r*68 + c4] = S4[idx];
    }
    if (tid < 64) BS[tid] = bias[tid];
    __syncthreads();

    int tx = tid & 15, ty = tid >> 4;
    float accY[8][4], accP[8][4], accB[8][4];
    #pragma unroll
    for (int r = 0; r < 8; r++)
        #pragma unroll
        for (int c = 0; c < 4; c++) { accY[r][c]=0.f; accP[r][c]=0.f; accB[r][c]=0.f; }

    #pragma unroll 4
    for (int k = 0; k < 64; k++) {
        float a[8];
        float4 a0 = *(const float4*)&XT[k*132 + ty*8];
        float4 a1 = *(const float4*)&XT[k*132 + ty*8 + 4];
        a[0]=a0.x; a[1]=a0.y; a[2]=a0.z; a[3]=a0.w;
        a[4]=a1.x; a[5]=a1.y; a[6]=a1.z; a[7]=a1.w;
        float4 wa = *(const float4*)&WA[k*68 + tx*4];
        float4 ww = *(const float4*)&WW[k*68 + tx*4];
        float4 ws = *(const float4*)&WS[k*68 + tx*4];
        #pragma unroll
        for (int r = 0; r < 8; r++) {
            accY[r][0] += a[r]*wa.x; accY[r][1] += a[r]*wa.y;
            accY[r][2] += a[r]*wa.z; accY[r][3] += a[r]*wa.w;
            accP[r][0] += a[r]*ww.x; accP[r][1] += a[r]*ww.y;
            accP[r][2] += a[r]*ww.z; accP[r][3] += a[r]*ww.w;
            accB[r][0] += a[r]*ws.x; accB[r][1] += a[r]*ws.y;
            accB[r][2] += a[r]*ws.z; accB[r][3] += a[r]*ws.w;
        }
    }

    float b0 = BS[tx*4+0], b1 = BS[tx*4+1], b2 = BS[tx*4+2], b3 = BS[tx*4+3];
    float s0 = SC[tx*4+0], s1 = SC[tx*4+1], s2 = SC[tx*4+2], s3 = SC[tx*4+3];
    #pragma unroll
    for (int r = 0; r < 8; r++) {
        size_t row = (size_t)row0 + ty*8 + r;
        *(float4*)&g_base[row*NF + tx*4] =
            make_float4(accB[r][0]+b0, accB[r][1]+b1, accB[r][2]+b2, accB[r][3]+b3);
        // plain fp16 of Y (B operand of GEMM1)
        unsigned short y0 = h16(accY[r][0]), y1 = h16(accY[r][1]);
        unsigned short y2 = h16(accY[r][2]), y3 = h16(accY[r][3]);
        *(uint2*)&g_Yh[row*NF + tx*4] =
            make_uint2((uint32_t)y0 | ((uint32_t)y1<<16),
                       (uint32_t)y2 | ((uint32_t)y3<<16));
        // fp16 hi/lo split of Y*s (A operand of GEMM1)
        unsigned short h[4], l[4];
        split2h(accY[r][0]*s0, h[0], l[0]);
        split2h(accY[r][1]*s1, h[1], l[1]);
        split2h(accY[r][2]*s2, h[2], l[2]);
        split2h(accY[r][3]*s3, h[3], l[3]);
        *(uint2*)&g_Ah[row*NF + tx*4] =
            make_uint2((uint32_t)h[0] | ((uint32_t)h[1]<<16),
                       (uint32_t)h[2] | ((uint32_t)h[3]<<16));
        *(uint2*)&g_Al[row*NF + tx*4] =
            make_uint2((uint32_t)l[0] | ((uint32_t)l[1]<<16),
                       (uint32_t)l[2] | ((uint32_t)l[3]<<16));
    }

    // stage accP, write transposed fp16 (XW)^T: PT[b][g][n]
    __syncthreads();
    float* Pst = sm;  // reuse XT area: 128 x 65 floats
    #pragma unroll
    for (int r = 0; r < 8; r++)
        #pragma unroll
        for (int c = 0; c < 4; c++)
            Pst[(ty*8+r)*65 + tx*4+c] = accP[r][c];
    __syncthreads();

    int g = tid >> 2, q = tid & 3;
    int b_ = row0 >> 10;
    int n0 = row0 & 1023;
    size_t baseT = ((size_t)b_*NF + g)*NN + n0 + q*32;
    #pragma unroll
    for (int i = 0; i < 32; i += 4) {
        unsigned short h[4];
        #pragma unroll
        for (int j = 0; j < 4; j++)
            h[j] = h16(Pst[(q*32 + i + j)*65 + g]);
        *(uint2*)&g_PTh[baseT + i] =
            make_uint2((uint32_t)h[0] | ((uint32_t)h[1]<<16),
                       (uint32_t)h[2] | ((uint32_t)h[3]<<16));
    }
}

// ---------------------------------------------------------------------------
// Main kernel: fp16 mma.sync, 2-term split (A-side hi/lo, B-side plain).
// Per CTA (batch b, 128-row tile bx); 8 warps 4(m) x 2(n).
// smem: A hi/lo 32K | S hi/lo 32K | B x2 16K | P x2 16K = 96KB, occ 2.
#define SA_H 0
#define SA_L 16384
#define SS_H 32768
#define SS_L 49152
#define SB0  65536
#define SB1  73728
#define SP0  81920
#define SP1  90112
#define SM_TOT 98304

// acc += Ah@B^T + Al@B^T over a 64-k tile (A 128x64 region, B 64x64 region)
__device__ __forceinline__ void gemm_tile2(uint32_t sb, uint32_t aH, uint32_t aL,
                                           uint32_t bH, int wm, int wn, int lane,
                                           float acc[2][4][4]) {
    int lr = lane & 15, lh = lane >> 4;
    #pragma unroll
    for (int kc = 0; kc < 4; kc++) {
        uint32_t colb = kc*32 + lh*16;
        uint32_t bh[4][2];
        #pragma unroll
        for (int np = 0; np < 2; np++) {
            uint32_t off = (uint32_t)(wn*32 + np*16 + lr)*128 + colb;
            uint32_t r0, r1, r2, r3;
            LDSM4(r0, r1, r2, r3, sb + bH + SWZ(off));
            bh[np*2][0]=r0; bh[np*2][1]=r2; bh[np*2+1][0]=r1; bh[np*2+1][1]=r3;
        }
        #pragma unroll
        for (int mi = 0; mi < 2; mi++) {
            uint32_t off = (uint32_t)(wm*32 + mi*16 + lr)*128 + colb;
            uint32_t ah[4], al[4];
            LDSM4(ah[0], ah[1], ah[2], ah[3], sb + aH + SWZ(off));
            LDSM4(al[0], al[1], al[2], al[3], sb + aL + SWZ(off));
            #pragma unroll
            for (int ni = 0; ni < 4; ni++) {
                mma16816(acc[mi][ni], ah, bh[ni]);
                mma16816(acc[mi][ni], al, bh[ni]);
            }
        }
    }
}

__global__ void __launch_bounds__(256, 2)
main_kernel(float* __restrict__ out) {
    extern __shared__ char smem[];
    uint32_t sb = smem_u32(smem);
    int tid = threadIdx.x, wid = tid >> 5, lane = tid & 31;
    int wm = wid >> 1, wn = wid & 1;
    int bx = blockIdx.x, b = blockIdx.y;

    // Build A tiles: copy g_Ah/g_Al rows into swizzled smem
    {
        int r = tid >> 1, hf = tid & 1;
        const unsigned short* src_g = hf ? g_Al : g_Ah;
        const uint4* src = (const uint4*)(src_g + ((size_t)(b*NN + bx*128 + r))*NF);
        char* dst = smem + (hf ? SA_L : SA_H);
        uint32_t rb = (uint32_t)r * 128;
        #pragma unroll
        for (int j = 0; j < 8; j++)
            *(uint4*)(dst + SWZ(rb + j*16)) = src[j];
    }

    // Prologue: load tile kt=0 into SB0/SP0
    int tlr = tid >> 2, tsg = tid & 3;
    {
        size_t yo = ((size_t)(b*NN + tlr))*NF + tsg*16;
        size_t po = ((size_t)(b*NF + tlr))*NN + tsg*16;
        uint4 b0 = *(const uint4*)(g_Yh + yo);
        uint4 b1 = *(const uint4*)(g_Yh + yo + 8);
        uint4 p0 = *(const uint4*)(g_PTh + po);
        uint4 p1 = *(const uint4*)(g_PTh + po + 8);
        uint32_t so = (uint32_t)tlr*128 + tsg*32;
        *(uint4*)(smem + SB0 + SWZ(so))      = b0;
        *(uint4*)(smem + SB0 + SWZ(so + 16)) = b1;
        *(uint4*)(smem + SP0 + SWZ(so))      = p0;
        *(uint4*)(smem + SP0 + SWZ(so + 16)) = p1;
    }
    __syncthreads();

    float oacc[2][4][4];
    #pragma unroll
    for (int mi = 0; mi < 2; mi++)
        #pragma unroll
        for (int ni = 0; ni < 4; ni++)
            #pragma unroll
            for (int d = 0; d < 4; d++) oacc[mi][ni][d] = 0.f;

    int lane4 = lane >> 2, lanec = (lane & 3) * 2;
    const uint32_t bufB[2] = {SB0, SB1};
    const uint32_t bufP[2] = {SP0, SP1};

    for (int kt = 0; kt < 16; kt++) {
        int cur = kt & 1, nxt = cur ^ 1;

        // Prefetch next tile into registers (hidden behind GEMM1)
        uint4 pb0, pb1, pp0, pp1;
        bool pf = (kt < 15);
        if (pf) {
            size_t yo = ((size_t)(b*NN + (kt+1)*64 + tlr))*NF + tsg*16;
            size_t po = ((size_t)(b*NF + tlr))*NN + (kt+1)*64 + tsg*16;
            pb0 = *(const uint4*)(g_Yh + yo);
            pb1 = *(const uint4*)(g_Yh + yo + 8);
            pp0 = *(const uint4*)(g_PTh + po);
            pp1 = *(const uint4*)(g_PTh + po + 8);
        }

        // GEMM1: S = A(hi,lo) @ Yk^T
        float sacc[2][4][4];
        #pragma unroll
        for (int mi = 0; mi < 2; mi++)
            #pragma unroll
            for (int ni = 0; ni < 4; ni++)
                #pragma unroll
                for (int d = 0; d < 4; d++) sacc[mi][ni][d] = 0.f;
        gemm_tile2(sb, SA_H, SA_L, bufB[cur], wm, wn, lane, sacc);

        // mid: leaky + diag-mask + fp16 split -> SS_H/SS_L; STS next B/P
        #pragma unroll
        for (int mi = 0; mi < 2; mi++)
            #pragma unroll
            for (int ni = 0; ni < 4; ni++) {
                int n = wn*32 + ni*8 + lanec;
                int jg = kt*64 + n;
                #pragma unroll
                for (int h = 0; h < 2; h++) {
                    int m = wm*32 + mi*16 + lane4 + h*8;
                    int ig = bx*128 + m;
                    float v0 = sacc[mi][ni][h*2];
                    float v1 = sacc[mi][ni][h*2+1];
                    v0 = (v0 > 0.f) ? v0 : 0.01f*v0;
                    v1 = (v1 > 0.f) ? v1 : 0.01f*v1;
                    if (ig == jg)     v0 = 0.f;
                    if (ig == jg + 1) v1 = 0.f;
                    unsigned short h0, h1, l0, l1;
                    split2h(v0, h0, l0); split2h(v1, h1, l1);
                    uint32_t off = SWZ((uint32_t)m*128 + n*2);
                    *(uint32_t*)(smem + SS_H + off) = (uint32_t)h0 | ((uint32_t)h1<<16);
                    *(uint32_t*)(smem + SS_L + off) = (uint32_t)l0 | ((uint32_t)l1<<16);
                }
            }
        if (pf) {
            uint32_t so = (uint32_t)tlr*128 + tsg*32;
            *(uint4*)(smem + bufB[nxt] + SWZ(so))      = pb0;
            *(uint4*)(smem + bufB[nxt] + SWZ(so + 16)) = pb1;
            *(uint4*)(smem + bufP[nxt] + SWZ(so))      = pp0;
            *(uint4*)(smem + bufP[nxt] + SWZ(so + 16)) = pp1;
        }
        __syncthreads();

        // GEMM2: O += S(hi,lo) @ P
        gemm_tile2(sb, SS_H, SS_L, bufP[cur], wm, wn, lane, oacc);
        __syncthreads();
    }

    // Epilogue: out = O + base
    #pragma unroll
    for (int mi = 0; mi < 2; mi++)
        #pragma unroll
        for (int ni = 0; ni < 4; ni++) {
            int n = wn*32 + ni*8 + lanec;
            #pragma unroll
            for (int h = 0; h < 2; h++) {
                int m = wm*32 + mi*16 + lane4 + h*8;
                size_t gi = ((size_t)(b*NN + bx*128 + m))*NF + n;
                float2 bb = *(const float2*)(g_base + gi);
                *(float2*)(out + gi) = make_float2(oacc[mi][ni][h*2]   + bb.x,
                                                   oacc[mi][ni][h*2+1] + bb.y);
            }
        }
}

// ---------------------------------------------------------------------------
extern "C" void kernel_launch(void* const* d_in, const int* in_sizes, int n_in,
                              void* d_out, int out_size) {
    const float* X     = (const float*)d_in[0];
    // d_in[1] = A (unused in forward)
    const float* W     = (const float*)d_in[2];
    const float* attW  = (const float*)d_in[3];
    const float* amat  = (const float*)d_in[4];
    const float* bias  = (const float*)d_in[5];
    const float* selfW = (const float*)d_in[6];
    float* out = (float*)d_out;

    size_t smem1 = (size_t)(64*132 + 3*64*68 + 64 + 64) * sizeof(float);
    cudaFuncSetAttribute((const void*)prep_kernel,
                         cudaFuncAttributeMaxDynamicSharedMemorySize, (int)smem1);
    cudaFuncSetAttribute((const void*)main_kernel,
                         cudaFuncAttributeMaxDynamicSharedMemorySize, SM_TOT);

    prep_kernel<<<NB*NN/128, 256, smem1>>>(X, W, attW, selfW, bias, amat);
    dim3 g2(NN/128, NB);
    main_kernel<<<g2, 256, SM_TOT>>>(out);
}

// round 7
// speedup vs baseline: 3.1378x; 1.2125x over previous
#include <cuda_runtime.h>
#include <cuda_fp16.h>
#include <cstdint>

#define NB 32
#define NN 1024
#define NF 64

// ---------------------------------------------------------------------------
// Device scratch (no runtime allocation allowed)
__device__ __align__(16) float g_base[NB*NN*NF];          // X@self_W + bias (fp32)
__device__ __align__(16) unsigned short g_Ah[NB*NN*NF];   // fp16 hi of (att_X * s) [b][n][f]
__device__ __align__(16) unsigned short g_Al[NB*NN*NF];   // fp16 lo
__device__ __align__(16) unsigned short g_Yh[NB*NN*NF];   // fp16 of att_X [b][n][f]
__device__ __align__(16) unsigned short g_PTh[NB*NF*NN];  // fp16 of (XW)^T [b][g][n]

// ---------------------------------------------------------------------------
#define SWZ(o) ((o) ^ (((o) >> 3) & 0x70))
// swizzled row base: row-part bits >=7, col-part <128 => SWZ(rb+c) = (rb|mask)^c
__device__ __forceinline__ uint32_t swz_row(uint32_t rowbytes) {
    return rowbytes | ((rowbytes >> 3) & 0x70);
}

__device__ __forceinline__ uint32_t smem_u32(const void* p) {
    uint32_t a;
    asm("{ .reg .u64 t; cvta.to.shared.u64 t, %1; cvt.u32.u64 %0, t; }"
        : "=r"(a) : "l"(p));
    return a;
}

#define LDSM4(r0, r1, r2, r3, addr) \
    asm volatile("ldmatrix.sync.aligned.m8n8.x4.shared.b16 {%0,%1,%2,%3}, [%4];" \
                 : "=r"(r0), "=r"(r1), "=r"(r2), "=r"(r3) : "r"(addr))

__device__ __forceinline__ void mma16816(float* d, const uint32_t* a,
                                         const uint32_t* b) {
    asm volatile(
        "mma.sync.aligned.m16n8k16.row.col.f32.f16.f16.f32 "
        "{%0,%1,%2,%3}, {%4,%5,%6,%7}, {%8,%9}, {%0,%1,%2,%3};"
        : "+f"(d[0]), "+f"(d[1]), "+f"(d[2]), "+f"(d[3])
        : "r"(a[0]), "r"(a[1]), "r"(a[2]), "r"(a[3]), "r"(b[0]), "r"(b[1]));
}

__device__ __forceinline__ void split2h(float a, unsigned short& h, unsigned short& l) {
    __half hh = __float2half_rn(a);
    float r = a - __half2float(hh);
    __half ll = __float2half_rn(r);
    h = __half_as_ushort(hh);
    l = __half_as_ushort(ll);
}
__device__ __forceinline__ unsigned short h16(float a) {
    return __half_as_ushort(__float2half_rn(a));
}

// ---------------------------------------------------------------------------
// prep: s = a.sum(0); Y = X@attW -> g_Yh (fp16), g_Ah/g_Al (fp16 split of Y*s);
//       PT = (X@W)^T -> g_PTh (fp16); base = X@selfW + bias (fp32)
__global__ void __launch_bounds__(256, 2)
prep_kernel(const float* __restrict__ X,
            const float* __restrict__ W,
            const float* __restrict__ attW,
            const float* __restrict__ selfW,
            const float* __restrict__ bias,
            const float* __restrict__ amat) {
    extern __shared__ float sm[];
    float* XT = sm;              // [64][132]
    float* WA = XT + 64*132;
    float* WW = WA + 64*68;
    float* WS = WW + 64*68;
    float* BS = WS + 64*68;      // [64] bias
    float* SC = BS + 64;         // [64] s
    int tid = threadIdx.x;
    int row0 = blockIdx.x * 128;

    if (tid < 64) {
        float s = 0.f;
        #pragma unroll 8
        for (int i = 0; i < NF; i++) s += amat[i*NF + tid];
        SC[tid] = s;
    }

    const float4* X4 = (const float4*)(X + (size_t)row0*NF);
    #pragma unroll
    for (int q = 0; q < 8; q++) {
        int idx = tid + q*256;
        int r  = idx >> 4;
        int c4 = (idx & 15) << 2;
        float4 v = X4[idx];
        XT[(c4+0)*132 + r] = v.x;
        XT[(c4+1)*132 + r] = v.y;
        XT[(c4+2)*132 + r] = v.z;
        XT[(c4+3)*132 + r] = v.w;
    }
    const float4* A4 = (const float4*)attW;
    const float4* W4 = (const float4*)W;
    const float4* S4 = (const float4*)selfW;
    #pragma unroll
    for (int q = 0; q < 4; q++) {
        int idx = tid + q*256;
        int r  = idx >> 4;
        int c4 = (idx & 15) << 2;
        *(float4*)&WA[r*68 + c4] = A4[idx];
        *(float4*)&WW[r*68 + c4] = W4[idx];
        *(float4*)&WS[r*68 + c4] = S4[idx];
    }
    if (tid < 64) BS[tid] = bias[tid];
    __syncthreads();

    int tx = tid & 15, ty = tid >> 4;
    float accY[8][4], accP[8][4], accB[8][4];
    #pragma unroll
    for (int r = 0; r < 8; r++)
        #pragma unroll
        for (int c = 0; c < 4; c++) { accY[r][c]=0.f; accP[r][c]=0.f; accB[r][c]=0.f; }

    #pragma unroll 4
    for (int k = 0; k < 64; k++) {
        float a[8];
        float4 a0 = *(const float4*)&XT[k*132 + ty*8];
        float4 a1 = *(const float4*)&XT[k*132 + ty*8 + 4];
        a[0]=a0.x; a[1]=a0.y; a[2]=a0.z; a[3]=a0.w;
        a[4]=a1.x; a[5]=a1.y; a[6]=a1.z; a[7]=a1.w;
        float4 wa = *(const float4*)&WA[k*68 + tx*4];
        float4 ww = *(const float4*)&WW[k*68 + tx*4];
        float4 ws = *(const float4*)&WS[k*68 + tx*4];
        #pragma unroll
        for (int r = 0; r < 8; r++) {
            accY[r][0] += a[r]*wa.x; accY[r][1] += a[r]*wa.y;
            accY[r][2] += a[r]*wa.z; accY[r][3] += a[r]*wa.w;
            accP[r][0] += a[r]*ww.x; accP[r][1] += a[r]*ww.y;
            accP[r][2] += a[r]*ww.z; accP[r][3] += a[r]*ww.w;
            accB[r][0] += a[r]*ws.x; accB[r][1] += a[r]*ws.y;
            accB[r][2] += a[r]*ws.z; accB[r][3] += a[r]*ws.w;
        }
    }

    float b0 = BS[tx*4+0], b1 = BS[tx*4+1], b2 = BS[tx*4+2], b3 = BS[tx*4+3];
    float s0 = SC[tx*4+0], s1 = SC[tx*4+1], s2 = SC[tx*4+2], s3 = SC[tx*4+3];
    #pragma unroll
    for (int r = 0; r < 8; r++) {
        size_t row = (size_t)row0 + ty*8 + r;
        *(float4*)&g_base[row*NF + tx*4] =
            make_float4(accB[r][0]+b0, accB[r][1]+b1, accB[r][2]+b2, accB[r][3]+b3);
        unsigned short y0 = h16(accY[r][0]), y1 = h16(accY[r][1]);
        unsigned short y2 = h16(accY[r][2]), y3 = h16(accY[r][3]);
        *(uint2*)&g_Yh[row*NF + tx*4] =
            make_uint2((uint32_t)y0 | ((uint32_t)y1<<16),
                       (uint32_t)y2 | ((uint32_t)y3<<16));
        unsigned short h[4], l[4];
        split2h(accY[r][0]*s0, h[0], l[0]);
        split2h(accY[r][1]*s1, h[1], l[1]);
        split2h(accY[r][2]*s2, h[2], l[2]);
        split2h(accY[r][3]*s3, h[3], l[3]);
        *(uint2*)&g_Ah[row*NF + tx*4] =
            make_uint2((uint32_t)h[0] | ((uint32_t)h[1]<<16),
                       (uint32_t)h[2] | ((uint32_t)h[3]<<16));
        *(uint2*)&g_Al[row*NF + tx*4] =
            make_uint2((uint32_t)l[0] | ((uint32_t)l[1]<<16),
                       (uint32_t)l[2] | ((uint32_t)l[3]<<16));
    }

    __syncthreads();
    float* Pst = sm;  // reuse XT area: 128 x 65 floats
    #pragma unroll
    for (int r = 0; r < 8; r++)
        #pragma unroll
        for (int c = 0; c < 4; c++)
            Pst[(ty*8+r)*65 + tx*4+c] = accP[r][c];
    __syncthreads();

    int g = tid >> 2, q = tid & 3;
    int b_ = row0 >> 10;
    int n0 = row0 & 1023;
    size_t baseT = ((size_t)b_*NF + g)*NN + n0 + q*32;
    #pragma unroll
    for (int i = 0; i < 32; i += 4) {
        unsigned short h[4];
        #pragma unroll
        for (int j = 0; j < 4; j++)
            h[j] = h16(Pst[(q*32 + i + j)*65 + g]);
        *(uint2*)&g_PTh[baseT + i] =
            make_uint2((uint32_t)h[0] | ((uint32_t)h[1]<<16),
                       (uint32_t)h[2] | ((uint32_t)h[3]<<16));
    }
}

// ---------------------------------------------------------------------------
// Main kernel: fp16 mma.sync. GEMM1 2-term (A hi/lo), GEMM2 1-term (S plain).
// Per CTA (batch b, 128-row tile bx); 8 warps 4(m) x 2(n).
// smem: A hi/lo 32K | S 16K | B x2 16K | P x2 16K = 80KB, occ 2.
#define SA_H 0
#define SA_L 16384
#define SS_  32768
#define SB0  49152
#define SB1  57344
#define SP0  65536
#define SP1  73728
#define SM_TOT 81920

// GEMM1: acc += Ah@B^T + Al@B^T (A 128x64 region hi/lo, B 64x64 region)
__device__ __forceinline__ void gemm_g1(uint32_t aH, uint32_t aL, uint32_t bB,
                                        const uint32_t* aRow, const uint32_t* bRow,
                                        uint32_t lh, float acc[2][4][4]) {
    #pragma unroll
    for (int kc = 0; kc < 4; kc++) {
        uint32_t colb = kc*32 + lh*16;
        uint32_t bh[4][2];
        #pragma unroll
        for (int np = 0; np < 2; np++) {
            uint32_t r0, r1, r2, r3;
            LDSM4(r0, r1, r2, r3, bB + (bRow[np] ^ colb));
            bh[np*2][0]=r0; bh[np*2][1]=r2; bh[np*2+1][0]=r1; bh[np*2+1][1]=r3;
        }
        #pragma unroll
        for (int mi = 0; mi < 2; mi++) {
            uint32_t axo = aRow[mi] ^ colb;
            uint32_t ah[4], al[4];
            LDSM4(ah[0], ah[1], ah[2], ah[3], aH + axo);
            LDSM4(al[0], al[1], al[2], al[3], aL + axo);
            #pragma unroll
            for (int ni = 0; ni < 4; ni++) {
                mma16816(acc[mi][ni], ah, bh[ni]);
                mma16816(acc[mi][ni], al, bh[ni]);
            }
        }
    }
}

// GEMM2: acc += S@P (S 128x64 region plain fp16, P 64x64 region)
__device__ __forceinline__ void gemm_g2(uint32_t aS, uint32_t bB,
                                        const uint32_t* aRow, const uint32_t* bRow,
                                        uint32_t lh, float acc[2][4][4]) {
    #pragma unroll
    for (int kc = 0; kc < 4; kc++) {
        uint32_t colb = kc*32 + lh*16;
        uint32_t bh[4][2];
        #pragma unroll
        for (int np = 0; np < 2; np++) {
            uint32_t r0, r1, r2, r3;
            LDSM4(r0, r1, r2, r3, bB + (bRow[np] ^ colb));
            bh[np*2][0]=r0; bh[np*2][1]=r2; bh[np*2+1][0]=r1; bh[np*2+1][1]=r3;
        }
        #pragma unroll
        for (int mi = 0; mi < 2; mi++) {
            uint32_t as[4];
            LDSM4(as[0], as[1], as[2], as[3], aS + (aRow[mi] ^ colb));
            #pragma unroll
            for (int ni = 0; ni < 4; ni++)
                mma16816(acc[mi][ni], as, bh[ni]);
        }
    }
}

__global__ void __launch_bounds__(256, 2)
main_kernel(float* __restrict__ out) {
    extern __shared__ char smem[];
    uint32_t sb = smem_u32(smem);
    int tid = threadIdx.x, wid = tid >> 5, lane = tid & 31;
    int wm = wid >> 1, wn = wid & 1;
    int bx = blockIdx.x, b = blockIdx.y;

    // Build A tiles: copy g_Ah/g_Al rows into swizzled smem
    {
        int r = tid >> 1, hf = tid & 1;
        const unsigned short* src_g = hf ? g_Al : g_Ah;
        const uint4* src = (const uint4*)(src_g + ((size_t)(b*NN + bx*128 + r))*NF);
        uint32_t dst = sb + (hf ? SA_L : SA_H) + swz_row((uint32_t)r * 128);
        #pragma unroll
        for (int j = 0; j < 8; j++)
            asm volatile("st.shared.v4.b32 [%0], {%1,%2,%3,%4};"
                         :: "r"(dst ^ (j*16)),
                            "r"(src[j].x), "r"(src[j].y),
                            "r"(src[j].z), "r"(src[j].w) : "memory");
    }

    // Prologue: load tile kt=0 into SB0/SP0
    int tlr = tid >> 2, tsg = tid & 3;
    uint32_t ldst = swz_row((uint32_t)tlr*128) ^ ((uint32_t)tsg*32);
    {
        size_t yo = ((size_t)(b*NN + tlr))*NF + tsg*16;
        size_t po = ((size_t)(b*NF + tlr))*NN + tsg*16;
        uint4 b0 = *(const uint4*)(g_Yh + yo);
        uint4 b1 = *(const uint4*)(g_Yh + yo + 8);
        uint4 p0 = *(const uint4*)(g_PTh + po);
        uint4 p1 = *(const uint4*)(g_PTh + po + 8);
        *(uint4*)(smem + SB0 + ldst)        = b0;
        *(uint4*)(smem + SB0 + (ldst ^ 16)) = b1;
        *(uint4*)(smem + SP0 + ldst)        = p0;
        *(uint4*)(smem + SP0 + (ldst ^ 16)) = p1;
    }
    __syncthreads();

    float oacc[2][4][4];
    #pragma unroll
    for (int mi = 0; mi < 2; mi++)
        #pragma unroll
        for (int ni = 0; ni < 4; ni++)
            #pragma unroll
            for (int d = 0; d < 4; d++) oacc[mi][ni][d] = 0.f;

    // precomputed swizzled row bases for ldmatrix
    uint32_t lr = lane & 15, lh = lane >> 4;
    uint32_t aRow[2], bRow[2], sRow[2];
    #pragma unroll
    for (int i = 0; i < 2; i++) {
        aRow[i] = swz_row((uint32_t)(wm*32 + i*16 + lr)*128);
        bRow[i] = swz_row((uint32_t)(wn*32 + i*16 + lr)*128);
    }
    // swizzled row bases for S stores (per h of each mi)
    int lane4 = lane >> 2, lanec = (lane & 3) * 2;
    #pragma unroll
    for (int mi = 0; mi < 2; mi++)
        sRow[mi] = swz_row((uint32_t)(wm*32 + mi*16 + lane4)*128);

    const uint32_t bufB[2] = {SB0, SB1};
    const uint32_t bufP[2] = {SP0, SP1};

    for (int kt = 0; kt < 16; kt++) {
        int cur = kt & 1, nxt = cur ^ 1;

        // Prefetch next tile into registers (hidden behind GEMM1)
        uint4 pb0, pb1, pp0, pp1;
        bool pf = (kt < 15);
        if (pf) {
            size_t yo = ((size_t)(b*NN + (kt+1)*64 + tlr))*NF + tsg*16;
            size_t po = ((size_t)(b*NF + tlr))*NN + (kt+1)*64 + tsg*16;
            pb0 = *(const uint4*)(g_Yh + yo);
            pb1 = *(const uint4*)(g_Yh + yo + 8);
            pp0 = *(const uint4*)(g_PTh + po);
            pp1 = *(const uint4*)(g_PTh + po + 8);
        }

        // GEMM1: S = A(hi,lo) @ Yk^T
        float sacc[2][4][4];
        #pragma unroll
        for (int mi = 0; mi < 2; mi++)
            #pragma unroll
            for (int ni = 0; ni < 4; ni++)
                #pragma unroll
                for (int d = 0; d < 4; d++) sacc[mi][ni][d] = 0.f;
        gemm_g1(sb + SA_H, sb + SA_L, sb + bufB[cur], aRow, bRow, lh, sacc);

        // mid: leaky + diag-mask + plain fp16 -> SS; STS next B/P
        #pragma unroll
        for (int mi = 0; mi < 2; mi++)
            #pragma unroll
            for (int ni = 0; ni < 4; ni++) {
                int n = wn*32 + ni*8 + lanec;
                int jg = kt*64 + n;
                #pragma unroll
                for (int h = 0; h < 2; h++) {
                    int m = wm*32 + mi*16 + lane4 + h*8;
                    int ig = bx*128 + m;
                    float v0 = sacc[mi][ni][h*2];
                    float v1 = sacc[mi][ni][h*2+1];
                    v0 = (v0 > 0.f) ? v0 : 0.01f*v0;
                    v1 = (v1 > 0.f) ? v1 : 0.01f*v1;
                    if (ig == jg)     v0 = 0.f;
                    if (ig == jg + 1) v1 = 0.f;
                    unsigned short h0 = h16(v0), h1 = h16(v1);
                    // row base for this h: sRow[mi] row is (..+lane4); h adds 8 rows = 1024 bytes
                    uint32_t off = (sRow[mi] + h*1024) ^ ((uint32_t)n*2);
                    *(uint32_t*)(smem + SS_ + off) = (uint32_t)h0 | ((uint32_t)h1<<16);
                }
            }
        if (pf) {
            *(uint4*)(smem + bufB[nxt] + ldst)        = pb0;
            *(uint4*)(smem + bufB[nxt] + (ldst ^ 16)) = pb1;
            *(uint4*)(smem + bufP[nxt] + ldst)        = pp0;
            *(uint4*)(smem + bufP[nxt] + (ldst ^ 16)) = pp1;
        }
        __syncthreads();

        // GEMM2: O += S @ P (1-term)
        gemm_g2(sb + SS_, sb + bufP[cur], aRow, bRow, lh, oacc);
        __syncthreads();
    }

    // Epilogue: out = O + base
    #pragma unroll
    for (int mi = 0; mi < 2; mi++)
        #pragma unroll
        for (int ni = 0; ni < 4; ni++) {
            int n = wn*32 + ni*8 + lanec;
            #pragma unroll
            for (int h = 0; h < 2; h++) {
                int m = wm*32 + mi*16 + lane4 + h*8;
                size_t gi = ((size_t)(b*NN + bx*128 + m))*NF + n;
                float2 bb = *(const float2*)(g_base + gi);
                *(float2*)(out + gi) = make_float2(oacc[mi][ni][h*2]   + bb.x,
                                                   oacc[mi][ni][h*2+1] + bb.y);
            }
        }
}

// ---------------------------------------------------------------------------
extern "C" void kernel_launch(void* const* d_in, const int* in_sizes, int n_in,
                              void* d_out, int out_size) {
    const float* X     = (const float*)d_in[0];
    // d_in[1] = A (unused in forward)
    const float* W     = (const float*)d_in[2];
    const float* attW  = (const float*)d_in[3];
    const float* amat  = (const float*)d_in[4];
    const float* bias  = (const float*)d_in[5];
    const float* selfW = (const float*)d_in[6];
    float* out = (float*)d_out;

    size_t smem1 = (size_t)(64*132 + 3*64*68 + 64 + 64) * sizeof(float);
    cudaFuncSetAttribute((const void*)prep_kernel,
                         cudaFuncAttributeMaxDynamicSharedMemorySize, (int)smem1);
    cudaFuncSetAttribute((const void*)main_kernel,
                         cudaFuncAttributeMaxDynamicSharedMemorySize, SM_TOT);

    prep_kernel<<<NB*NN/128, 256, smem1>>>(X, W, attW, selfW, bias, amat);
    dim3 g2(NN/128, NB);
    main_kernel<<<g2, 256, SM_TOT>>>(out);
}

// round 8
// speedup vs baseline: 3.3842x; 1.0785x over previous
#include <cuda_runtime.h>
#include <cuda_fp16.h>
#include <cstdint>

#define NB 32
#define NN 1024
#define NF 64

// ---------------------------------------------------------------------------
// Device scratch (no runtime allocation allowed)
__device__ __align__(16) float g_base[NB*NN*NF];          // X@self_W + bias (fp32)
__device__ __align__(16) unsigned short g_Ah[NB*NN*NF];   // fp16 hi of (att_X * s) [b][n][f]
__device__ __align__(16) unsigned short g_Al[NB*NN*NF];   // fp16 lo
__device__ __align__(16) unsigned short g_Yh[NB*NN*NF];   // fp16 of att_X [b][n][f]
__device__ __align__(16) unsigned short g_PTh[NB*NF*NN];  // fp16 of (XW)^T [b][g][n]

// ---------------------------------------------------------------------------
#define SWZ(o) ((o) ^ (((o) >> 3) & 0x70))
__device__ __forceinline__ uint32_t swz_row(uint32_t rowbytes) {
    return rowbytes | ((rowbytes >> 3) & 0x70);
}

__device__ __forceinline__ uint32_t smem_u32(const void* p) {
    uint32_t a;
    asm("{ .reg .u64 t; cvta.to.shared.u64 t, %1; cvt.u32.u64 %0, t; }"
        : "=r"(a) : "l"(p));
    return a;
}

#define LDSM4(r0, r1, r2, r3, addr) \
    asm volatile("ldmatrix.sync.aligned.m8n8.x4.shared.b16 {%0,%1,%2,%3}, [%4];" \
                 : "=r"(r0), "=r"(r1), "=r"(r2), "=r"(r3) : "r"(addr))

#define CPASYNC16(dst, src) \
    asm volatile("cp.async.cg.shared.global [%0], [%1], 16;" \
                 :: "r"(dst), "l"(src) : "memory")
#define CPCOMMIT() asm volatile("cp.async.commit_group;" ::: "memory")
#define CPWAIT0()  asm volatile("cp.async.wait_group 0;" ::: "memory")

__device__ __forceinline__ void mma16816(float* d, const uint32_t* a,
                                         const uint32_t* b) {
    asm volatile(
        "mma.sync.aligned.m16n8k16.row.col.f32.f16.f16.f32 "
        "{%0,%1,%2,%3}, {%4,%5,%6,%7}, {%8,%9}, {%0,%1,%2,%3};"
        : "+f"(d[0]), "+f"(d[1]), "+f"(d[2]), "+f"(d[3])
        : "r"(a[0]), "r"(a[1]), "r"(a[2]), "r"(a[3]), "r"(b[0]), "r"(b[1]));
}

__device__ __forceinline__ void split2h(float a, unsigned short& h, unsigned short& l) {
    __half hh = __float2half_rn(a);
    float r = a - __half2float(hh);
    __half ll = __float2half_rn(r);
    h = __half_as_ushort(hh);
    l = __half_as_ushort(ll);
}
__device__ __forceinline__ unsigned short h16(float a) {
    return __half_as_ushort(__float2half_rn(a));
}
__device__ __forceinline__ uint32_t packh2(float lo, float hi) {
    __half2 h2 = __floats2half2_rn(lo, hi);
    return *reinterpret_cast<uint32_t*>(&h2);
}

// ---------------------------------------------------------------------------
// prep: s = a.sum(0); Y = X@attW -> g_Yh (fp16), g_Ah/g_Al (fp16 split of Y*s);
//       PT = (X@W)^T -> g_PTh (fp16); base = X@selfW + bias (fp32)
__global__ void __launch_bounds__(256, 2)
prep_kernel(const float* __restrict__ X,
            const float* __restrict__ W,
            const float* __restrict__ attW,
            const float* __restrict__ selfW,
            const float* __restrict__ bias,
            const float* __restrict__ amat) {
    extern __shared__ float sm[];
    float* XT = sm;              // [64][132]
    float* WA = XT + 64*132;
    float* WW = WA + 64*68;
    float* WS = WW + 64*68;
    float* BS = WS + 64*68;      // [64] bias
    float* SC = BS + 64;         // [64] s
    int tid = threadIdx.x;
    int row0 = blockIdx.x * 128;

    if (tid < 64) {
        float s = 0.f;
        #pragma unroll 8
        for (int i = 0; i < NF; i++) s += amat[i*NF + tid];
        SC[tid] = s;
    }

    const float4* X4 = (const float4*)(X + (size_t)row0*NF);
    #pragma unroll
    for (int q = 0; q < 8; q++) {
        int idx = tid + q*256;
        int r  = idx >> 4;
        int c4 = (idx & 15) << 2;
        float4 v = X4[idx];
        XT[(c4+0)*132 + r] = v.x;
        XT[(c4+1)*132 + r] = v.y;
        XT[(c4+2)*132 + r] = v.z;
        XT[(c4+3)*132 + r] = v.w;
    }
    const float4* A4 = (const float4*)attW;
    const float4* W4 = (const float4*)W;
    const float4* S4 = (const float4*)selfW;
    #pragma unroll
    for (int q = 0; q < 4; q++) {
        int idx = tid + q*256;
        int r  = idx >> 4;
        int c4 = (idx & 15) << 2;
        *(float4*)&WA[r*68 + c4] = A4[idx];
        *(float4*)&WW[r*68 + c4] = W4[idx];
        *(float4*)&WS[r*68 + c4] = S4[idx];
    }
    if (tid < 64) BS[tid] = bias[tid];
    __syncthreads();

    int tx = tid & 15, ty = tid >> 4;
    float accY[8][4], accP[8][4], accB[8][4];
    #pragma unroll
    for (int r = 0; r < 8; r++)
        #pragma unroll
        for (int c = 0; c < 4; c++) { accY[r][c]=0.f; accP[r][c]=0.f; accB[r][c]=0.f; }

    #pragma unroll 4
    for (int k = 0; k < 64; k++) {
        float a[8];
        float4 a0 = *(const float4*)&XT[k*132 + ty*8];
        float4 a1 = *(const float4*)&XT[k*132 + ty*8 + 4];
        a[0]=a0.x; a[1]=a0.y; a[2]=a0.z; a[3]=a0.w;
        a[4]=a1.x; a[5]=a1.y; a[6]=a1.z; a[7]=a1.w;
        float4 wa = *(const float4*)&WA[k*68 + tx*4];
        float4 ww = *(const float4*)&WW[k*68 + tx*4];
        float4 ws = *(const float4*)&WS[k*68 + tx*4];
        #pragma unroll
        for (int r = 0; r < 8; r++) {
            accY[r][0] += a[r]*wa.x; accY[r][1] += a[r]*wa.y;
            accY[r][2] += a[r]*wa.z; accY[r][3] += a[r]*wa.w;
            accP[r][0] += a[r]*ww.x; accP[r][1] += a[r]*ww.y;
            accP[r][2] += a[r]*ww.z; accP[r][3] += a[r]*ww.w;
            accB[r][0] += a[r]*ws.x; accB[r][1] += a[r]*ws.y;
            accB[r][2] += a[r]*ws.z; accB[r][3] += a[r]*ws.w;
        }
    }

    float b0 = BS[tx*4+0], b1 = BS[tx*4+1], b2 = BS[tx*4+2], b3 = BS[tx*4+3];
    float s0 = SC[tx*4+0], s1 = SC[tx*4+1], s2 = SC[tx*4+2], s3 = SC[tx*4+3];
    #pragma unroll
    for (int r = 0; r < 8; r++) {
        size_t row = (size_t)row0 + ty*8 + r;
        *(float4*)&g_base[row*NF + tx*4] =
            make_float4(accB[r][0]+b0, accB[r][1]+b1, accB[r][2]+b2, accB[r][3]+b3);
        unsigned short y0 = h16(accY[r][0]), y1 = h16(accY[r][1]);
        unsigned short y2 = h16(accY[r][2]), y3 = h16(accY[r][3]);
        *(uint2*)&g_Yh[row*NF + tx*4] =
            make_uint2((uint32_t)y0 | ((uint32_t)y1<<16),
                       (uint32_t)y2 | ((uint32_t)y3<<16));
        unsigned short h[4], l[4];
        split2h(accY[r][0]*s0, h[0], l[0]);
        split2h(accY[r][1]*s1, h[1], l[1]);
        split2h(accY[r][2]*s2, h[2], l[2]);
        split2h(accY[r][3]*s3, h[3], l[3]);
        *(uint2*)&g_Ah[row*NF + tx*4] =
            make_uint2((uint32_t)h[0] | ((uint32_t)h[1]<<16),
                       (uint32_t)h[2] | ((uint32_t)h[3]<<16));
        *(uint2*)&g_Al[row*NF + tx*4] =
            make_uint2((uint32_t)l[0] | ((uint32_t)l[1]<<16),
                       (uint32_t)l[2] | ((uint32_t)l[3]<<16));
    }

    __syncthreads();
    float* Pst = sm;  // reuse XT area: 128 x 65 floats
    #pragma unroll
    for (int r = 0; r < 8; r++)
        #pragma unroll
        for (int c = 0; c < 4; c++)
            Pst[(ty*8+r)*65 + tx*4+c] = accP[r][c];
    __syncthreads();

    int g = tid >> 2, q = tid & 3;
    int b_ = row0 >> 10;
    int n0 = row0 & 1023;
    size_t baseT = ((size_t)b_*NF + g)*NN + n0 + q*32;
    #pragma unroll
    for (int i = 0; i < 32; i += 4) {
        unsigned short h[4];
        #pragma unroll
        for (int j = 0; j < 4; j++)
            h[j] = h16(Pst[(q*32 + i + j)*65 + g]);
        *(uint2*)&g_PTh[baseT + i] =
            make_uint2((uint32_t)h[0] | ((uint32_t)h[1]<<16),
                       (uint32_t)h[2] | ((uint32_t)h[3]<<16));
    }
}

// ---------------------------------------------------------------------------
// Main kernel: 8 warps x (16 m-rows, full 64 n). GEMM1 2-term (A hi/lo hoisted
// to registers), S passed GEMM1->GEMM2 entirely in registers (C-frag == A-frag
// identity), B/P tiles via cp.async double buffer. One syncthreads per k-tile.
// smem: A hi/lo 32K | B x2 16K | P x2 16K = 64KB, occ 2.
#define SA_H 0
#define SA_L 16384
#define SB0  32768
#define SB1  40960
#define SP0  49152
#define SP1  57344
#define SM_TOT 65536

__global__ void __launch_bounds__(256, 2)
main_kernel(float* __restrict__ out) {
    extern __shared__ char smem[];
    uint32_t sb = smem_u32(smem);
    int tid = threadIdx.x, wid = tid >> 5, lane = tid & 31;
    int bx = blockIdx.x, b = blockIdx.y;

    // Build A tile (Yi hi/lo) into swizzled smem
    {
        int r = tid >> 1, hf = tid & 1;
        const unsigned short* src_g = hf ? g_Al : g_Ah;
        const uint4* src = (const uint4*)(src_g + ((size_t)(b*NN + bx*128 + r))*NF);
        uint32_t dst = sb + (hf ? SA_L : SA_H) + swz_row((uint32_t)r * 128);
        #pragma unroll
        for (int j = 0; j < 8; j++)
            asm volatile("st.shared.v4.b32 [%0], {%1,%2,%3,%4};"
                         :: "r"(dst ^ (j*16)),
                            "r"(src[j].x), "r"(src[j].y),
                            "r"(src[j].z), "r"(src[j].w) : "memory");
    }

    // cp.async tile kt=0 into SB0/SP0
    int tlr = tid >> 2, tsg = tid & 3;
    uint32_t ldst = swz_row((uint32_t)tlr*128) ^ ((uint32_t)tsg*32);
    {
        const char* yg = (const char*)(g_Yh + ((size_t)(b*NN + tlr))*NF + tsg*16);
        const char* pg = (const char*)(g_PTh + ((size_t)(b*NF + tlr))*NN + tsg*16);
        CPASYNC16(sb + SB0 + ldst,        yg);
        CPASYNC16(sb + SB0 + (ldst^16),   yg + 16);
        CPASYNC16(sb + SP0 + ldst,        pg);
        CPASYNC16(sb + SP0 + (ldst^16),   pg + 16);
        CPCOMMIT();
    }
    __syncthreads();   // A tile visible

    // Hoist A fragments (16 m-rows x 64 k, hi+lo) into registers: 32 regs
    uint32_t lr = lane & 15, lh = lane >> 4;
    uint32_t aRowB = swz_row((uint32_t)(wid*16 + lr)*128);
    uint32_t aH[4][4], aL[4][4];
    #pragma unroll
    for (int kc = 0; kc < 4; kc++) {
        uint32_t axo = aRowB ^ ((uint32_t)(kc*32 + lh*16));
        LDSM4(aH[kc][0], aH[kc][1], aH[kc][2], aH[kc][3], sb + SA_H + axo);
        LDSM4(aL[kc][0], aL[kc][1], aL[kc][2], aL[kc][3], sb + SA_L + axo);
    }

    // B-row bases (shared by Yk and P tiles: both 64 rows x 128B)
    uint32_t bRow[4];
    #pragma unroll
    for (int np = 0; np < 4; np++)
        bRow[np] = swz_row((uint32_t)(np*16 + lr)*128);

    float oacc[8][4];
    #pragma unroll
    for (int ni = 0; ni < 8; ni++)
        #pragma unroll
        for (int d = 0; d < 4; d++) oacc[ni][d] = 0.f;

    int lane4 = lane >> 2, lanec = (lane & 3) * 2;
    int m0 = bx*128 + wid*16 + lane4;     // global row of c0/c1
    const uint32_t bufB[2] = {SB0, SB1};
    const uint32_t bufP[2] = {SP0, SP1};

    for (int kt = 0; kt < 16; kt++) {
        int cur = kt & 1, nxt = cur ^ 1;

        CPWAIT0();
        __syncthreads();   // tile kt visible to all; all done with buffer nxt

        if (kt < 15) {
            const char* yg = (const char*)(g_Yh +
                ((size_t)(b*NN + (kt+1)*64 + tlr))*NF + tsg*16);
            const char* pg = (const char*)(g_PTh +
                ((size_t)(b*NF + tlr))*NN + (kt+1)*64 + tsg*16);
            CPASYNC16(sb + bufB[nxt] + ldst,      yg);
            CPASYNC16(sb + bufB[nxt] + (ldst^16), yg + 16);
            CPASYNC16(sb + bufP[nxt] + ldst,      pg);
            CPASYNC16(sb + bufP[nxt] + (ldst^16), pg + 16);
            CPCOMMIT();
        }

        // GEMM1: S = A(hi,lo) @ Yk^T   (B loads only; A in registers)
        float sacc[8][4];
        #pragma unroll
        for (int ni = 0; ni < 8; ni++)
            #pragma unroll
            for (int d = 0; d < 4; d++) sacc[ni][d] = 0.f;
        #pragma unroll
        for (int kc = 0; kc < 4; kc++) {
            uint32_t colb = (uint32_t)(kc*32 + lh*16);
            uint32_t bh[8][2];
            #pragma unroll
            for (int np = 0; np < 4; np++) {
                uint32_t r0, r1, r2, r3;
                LDSM4(r0, r1, r2, r3, sb + bufB[cur] + (bRow[np] ^ colb));
                bh[np*2][0]=r0; bh[np*2][1]=r2;
                bh[np*2+1][0]=r1; bh[np*2+1][1]=r3;
            }
            #pragma unroll
            for (int ni = 0; ni < 8; ni++) {
                mma16816(sacc[ni], aH[kc], bh[ni]);
                mma16816(sacc[ni], aL[kc], bh[ni]);
            }
        }

        // Register pass: leaky + diag-mask + pack C-frags into A-frags
        uint32_t aF[4][4];
        #pragma unroll
        for (int ni = 0; ni < 8; ni++) {
            int jg = kt*64 + ni*8 + lanec;
            float v0 = sacc[ni][0], v1 = sacc[ni][1];
            float v2 = sacc[ni][2], v3 = sacc[ni][3];
            v0 = (v0 > 0.f) ? v0 : 0.01f*v0;
            v1 = (v1 > 0.f) ? v1 : 0.01f*v1;
            v2 = (v2 > 0.f) ? v2 : 0.01f*v2;
            v3 = (v3 > 0.f) ? v3 : 0.01f*v3;
            if (m0     == jg)     v0 = 0.f;
            if (m0     == jg + 1) v1 = 0.f;
            if (m0 + 8 == jg)     v2 = 0.f;
            if (m0 + 8 == jg + 1) v3 = 0.f;
            aF[ni >> 1][(ni & 1)*2 + 0] = packh2(v0, v1);
            aF[ni >> 1][(ni & 1)*2 + 1] = packh2(v2, v3);
        }

        // GEMM2: O += S @ P   (S in registers, P loads only)
        #pragma unroll
        for (int kc = 0; kc < 4; kc++) {
            uint32_t colb = (uint32_t)(kc*32 + lh*16);
            uint32_t bh[8][2];
            #pragma unroll
            for (int np = 0; np < 4; np++) {
                uint32_t r0, r1, r2, r3;
                LDSM4(r0, r1, r2, r3, sb + bufP[cur] + (bRow[np] ^ colb));
                bh[np*2][0]=r0; bh[np*2][1]=r2;
                bh[np*2+1][0]=r1; bh[np*2+1][1]=r3;
            }
            #pragma unroll
            for (int ni = 0; ni < 8; ni++)
                mma16816(oacc[ni], aF[kc], bh[ni]);
        }
    }

    // Epilogue: out = O + base
    #pragma unroll
    for (int ni = 0; ni < 8; ni++) {
        int n = ni*8 + lanec;
        size_t gi0 = ((size_t)(b*NN + m0))*NF + n;
        size_t gi1 = ((size_t)(b*NN + m0 + 8))*NF + n;
        float2 b0 = *(const float2*)(g_base + gi0);
        float2 b1 = *(const float2*)(g_base + gi1);
        *(float2*)(out + gi0) = make_float2(oacc[ni][0] + b0.x, oacc[ni][1] + b0.y);
        *(float2*)(out + gi1) = make_float2(oacc[ni][2] + b1.x, oacc[ni][3] + b1.y);
    }
}

// ---------------------------------------------------------------------------
extern "C" void kernel_launch(void* const* d_in, const int* in_sizes, int n_in,
                              void* d_out, int out_size) {
    const float* X     = (const float*)d_in[0];
    // d_in[1] = A (unused in forward)
    const float* W     = (const float*)d_in[2];
    const float* attW  = (const float*)d_in[3];
    const float* amat  = (const float*)d_in[4];
    const float* bias  = (const float*)d_in[5];
    const float* selfW = (const float*)d_in[6];
    float* out = (float*)d_out;

    size_t smem1 = (size_t)(64*132 + 3*64*68 + 64 + 64) * sizeof(float);
    cudaFuncSetAttribute((const void*)prep_kernel,
                         cudaFuncAttributeMaxDynamicSharedMemorySize, (int)smem1);
    cudaFuncSetAttribute((const void*)main_kernel,
                         cudaFuncAttributeMaxDynamicSharedMemorySize, SM_TOT);

    prep_kernel<<<NB*NN/128, 256, smem1>>>(X, W, attW, selfW, bias, amat);
    dim3 g2(NN/128, NB);
    main_kernel<<<g2, 256, SM_TOT>>>(out);
}

// round 9
// speedup vs baseline: 4.5414x; 1.3419x over previous
#include <cuda_runtime.h>
#include <cuda_fp16.h>
#include <cstdint>

#define NB 32
#define NN 1024
#define NF 64

// ---------------------------------------------------------------------------
// Device scratch (no runtime allocation allowed)
__device__ __align__(16) float g_base[NB*NN*NF];          // X@self_W + bias (fp32)
__device__ __align__(16) unsigned short g_Ah[NB*NN*NF];   // fp16 of (att_X * s) [b][n][f]
__device__ __align__(16) unsigned short g_Yh[NB*NN*NF];   // fp16 of att_X [b][n][f]
__device__ __align__(16) unsigned short g_PTh[NB*NF*NN];  // fp16 of (XW)^T [b][g][n]

// ---------------------------------------------------------------------------
__device__ __forceinline__ uint32_t swz_row(uint32_t rowbytes) {
    return rowbytes | ((rowbytes >> 3) & 0x70);
}
__device__ __forceinline__ uint32_t smem_u32(const void* p) {
    uint32_t a;
    asm("{ .reg .u64 t; cvta.to.shared.u64 t, %1; cvt.u32.u64 %0, t; }"
        : "=r"(a) : "l"(p));
    return a;
}

#define LDSM4(r0, r1, r2, r3, addr) \
    asm volatile("ldmatrix.sync.aligned.m8n8.x4.shared.b16 {%0,%1,%2,%3}, [%4];" \
                 : "=r"(r0), "=r"(r1), "=r"(r2), "=r"(r3) : "r"(addr))

#define CPASYNC16(dst, src) \
    asm volatile("cp.async.cg.shared.global [%0], [%1], 16;" \
                 :: "r"(dst), "l"(src) : "memory")
#define CPCOMMIT() asm volatile("cp.async.commit_group;" ::: "memory")
#define CPWAIT0()  asm volatile("cp.async.wait_group 0;" ::: "memory")

__device__ __forceinline__ void mma16816(float* d, const uint32_t* a,
                                         const uint32_t* b) {
    asm volatile(
        "mma.sync.aligned.m16n8k16.row.col.f32.f16.f16.f32 "
        "{%0,%1,%2,%3}, {%4,%5,%6,%7}, {%8,%9}, {%0,%1,%2,%3};"
        : "+f"(d[0]), "+f"(d[1]), "+f"(d[2]), "+f"(d[3])
        : "r"(a[0]), "r"(a[1]), "r"(a[2]), "r"(a[3]), "r"(b[0]), "r"(b[1]));
}

__device__ __forceinline__ void split2h(float a, unsigned short& h, unsigned short& l) {
    __half hh = __float2half_rn(a);
    float r = a - __half2float(hh);
    __half ll = __float2half_rn(r);
    h = __half_as_ushort(hh);
    l = __half_as_ushort(ll);
}
__device__ __forceinline__ uint32_t packh2(float lo, float hi) {
    __half2 h2 = __floats2half2_rn(lo, hi);
    return *reinterpret_cast<uint32_t*>(&h2);
}

// ---------------------------------------------------------------------------
// prep (tensor-core): per CTA = 128 rows. Split X into fp16 hi/lo; transpose+
// split 3 weight matrices; 3-term fp16 GEMMs (fp32-class accuracy) produce:
//   Y -> g_Yh (fp16), g_Ah = fp16(Y*s);  P -> g_PTh transposed fp16;
//   base = X@selfW + bias -> g_base fp32.
// smem bytes:
#define PX_H   0
#define PX_L   16384
#define PW0_H  32768
#define PW0_L  40960
#define PW1_H  49152
#define PW1_L  57344
#define PW2_H  65536
#define PW2_L  73728
#define PSC    81920
#define PBS    82176
#define PSM_TOT 82432
#define PTMP   0          // reuse X region after fragment hoist (128 x 132B)

__global__ void __launch_bounds__(256, 2)
prep_kernel(const float* __restrict__ X,
            const float* __restrict__ W,
            const float* __restrict__ attW,
            const float* __restrict__ selfW,
            const float* __restrict__ bias,
            const float* __restrict__ amat) {
    extern __shared__ char psm[];
    uint32_t sb = smem_u32(psm);
    int tid = threadIdx.x, wid = tid >> 5, lane = tid & 31;
    int row0 = blockIdx.x * 128;                   // global row in [0, 32768)

    // s and bias into smem
    if (tid < 64) {
        float s = 0.f;
        #pragma unroll 8
        for (int i = 0; i < NF; i++) s += amat[i*NF + tid];
        *(float*)(psm + PSC + tid*4) = s;
        *(float*)(psm + PBS + tid*4) = bias[tid];
    }

    // X tile -> fp16 hi/lo, swizzled
    {
        int r = tid >> 1, hf = tid & 1;
        const float4* xs = (const float4*)(X + (size_t)(row0 + r)*NF + hf*32);
        uint32_t rbase = swz_row((uint32_t)r * 128);
        #pragma unroll
        for (int j = 0; j < 4; j++) {
            float4 v0 = xs[j*2], v1 = xs[j*2+1];
            unsigned short h[8], l[8];
            split2h(v0.x, h[0], l[0]); split2h(v0.y, h[1], l[1]);
            split2h(v0.z, h[2], l[2]); split2h(v0.w, h[3], l[3]);
            split2h(v1.x, h[4], l[4]); split2h(v1.y, h[5], l[5]);
            split2h(v1.z, h[6], l[6]); split2h(v1.w, h[7], l[7]);
            uint32_t off = rbase ^ ((uint32_t)(hf*64 + j*16));
            *(uint4*)(psm + PX_H + off) = make_uint4(
                (uint32_t)h[0] | ((uint32_t)h[1]<<16), (uint32_t)h[2] | ((uint32_t)h[3]<<16),
                (uint32_t)h[4] | ((uint32_t)h[5]<<16), (uint32_t)h[6] | ((uint32_t)h[7]<<16));
            *(uint4*)(psm + PX_L + off) = make_uint4(
                (uint32_t)l[0] | ((uint32_t)l[1]<<16), (uint32_t)l[2] | ((uint32_t)l[3]<<16),
                (uint32_t)l[4] | ((uint32_t)l[5]<<16), (uint32_t)l[6] | ((uint32_t)l[7]<<16));
        }
    }

    // Weights: transposed (Wt[n][k] = W[k][n]) + split, swizzled
    {
        int n = tid >> 2, q = tid & 3;
        uint32_t rb = swz_row((uint32_t)n * 128) ^ ((uint32_t)q * 32);
        #pragma unroll
        for (int w = 0; w < 3; w++) {
            const float* Wp = (w == 0) ? attW : (w == 1) ? W : selfW;
            uint32_t hb = (w == 0) ? PW0_H : (w == 1) ? PW1_H : PW2_H;
            unsigned short h[16], l[16];
            #pragma unroll
            for (int i = 0; i < 16; i++)
                split2h(Wp[(q*16 + i)*NF + n], h[i], l[i]);
            uint32_t wh[8], wl[8];
            #pragma unroll
            for (int i = 0; i < 8; i++) {
                wh[i] = (uint32_t)h[2*i] | ((uint32_t)h[2*i+1] << 16);
                wl[i] = (uint32_t)l[2*i] | ((uint32_t)l[2*i+1] << 16);
            }
            *(uint4*)(psm + hb + rb)               = make_uint4(wh[0], wh[1], wh[2], wh[3]);
            *(uint4*)(psm + hb + (rb ^ 16))        = make_uint4(wh[4], wh[5], wh[6], wh[7]);
            *(uint4*)(psm + hb + 8192 + rb)        = make_uint4(wl[0], wl[1], wl[2], wl[3]);
            *(uint4*)(psm + hb + 8192 + (rb ^ 16)) = make_uint4(wl[4], wl[5], wl[6], wl[7]);
        }
    }
    __syncthreads();

    // Hoist X fragments
    uint32_t lr = lane & 15, lh = lane >> 4;
    uint32_t aRowB = swz_row((uint32_t)(wid*16 + lr)*128);
    uint32_t xh[4][4], xl[4][4];
    #pragma unroll
    for (int kc = 0; kc < 4; kc++) {
        uint32_t axo = aRowB ^ ((uint32_t)(kc*32 + lh*16));
        LDSM4(xh[kc][0], xh[kc][1], xh[kc][2], xh[kc][3], sb + PX_H + axo);
        LDSM4(xl[kc][0], xl[kc][1], xl[kc][2], xl[kc][3], sb + PX_L + axo);
    }
    uint32_t bRow[4];
    #pragma unroll
    for (int np = 0; np < 4; np++)
        bRow[np] = swz_row((uint32_t)(np*16 + lr)*128);
    __syncthreads();   // everyone done reading X region before PTMP overwrite

    int lane4 = lane >> 2, lanec = (lane & 3)*2;
    int m0l = wid*16 + lane4;                       // local row

    float cacc[8][4];

    // ---- 3-term GEMM macro: cacc = Xh@Wth + Xh@Wtl + Xl@Wth
#define PGEMM3(WHOFF) do { \
        _Pragma("unroll") \
        for (int ni = 0; ni < 8; ni++) \
            _Pragma("unroll") \
            for (int d = 0; d < 4; d++) cacc[ni][d] = 0.f; \
        _Pragma("unroll") \
        for (int kc = 0; kc < 4; kc++) { \
            uint32_t colb = (uint32_t)(kc*32 + lh*16); \
            uint32_t bh[8][2], bl[8][2]; \
            _Pragma("unroll") \
            for (int np = 0; np < 4; np++) { \
                uint32_t r0, r1, r2, r3; \
                LDSM4(r0, r1, r2, r3, sb + (WHOFF) + (bRow[np] ^ colb)); \
                bh[np*2][0]=r0; bh[np*2][1]=r2; bh[np*2+1][0]=r1; bh[np*2+1][1]=r3; \
                LDSM4(r0, r1, r2, r3, sb + (WHOFF) + 8192 + (bRow[np] ^ colb)); \
                bl[np*2][0]=r0; bl[np*2][1]=r2; bl[np*2+1][0]=r1; bl[np*2+1][1]=r3; \
            } \
            _Pragma("unroll") \
            for (int ni = 0; ni < 8; ni++) { \
                mma16816(cacc[ni], xh[kc], bh[ni]); \
                mma16816(cacc[ni], xh[kc], bl[ni]); \
                mma16816(cacc[ni], xl[kc], bh[ni]); \
            } \
        } \
    } while (0)

    // ---- P = X@W -> staged transpose -> g_PTh
    PGEMM3(PW1_H);
    #pragma unroll
    for (int ni = 0; ni < 8; ni++) {
        int n = ni*8 + lanec;
        *(uint32_t*)(psm + PTMP + (uint32_t)m0l*132 + n*2)     = packh2(cacc[ni][0], cacc[ni][1]);
        *(uint32_t*)(psm + PTMP + (uint32_t)(m0l+8)*132 + n*2) = packh2(cacc[ni][2], cacc[ni][3]);
    }
    __syncthreads();
    {
        int g = tid >> 2, q = tid & 3;
        int b_ = row0 >> 10, n0 = row0 & 1023;
        size_t baseT = ((size_t)b_*NF + g)*NN + n0 + q*32;
        uint32_t wds[16];
        #pragma unroll
        for (int i = 0; i < 16; i++) {
            unsigned short u0 = *(unsigned short*)(psm + PTMP + (uint32_t)(q*32 + i*2    )*132 + g*2);
            unsigned short u1 = *(unsigned short*)(psm + PTMP + (uint32_t)(q*32 + i*2 + 1)*132 + g*2);
            wds[i] = (uint32_t)u0 | ((uint32_t)u1 << 16);
        }
        uint4* dst = (uint4*)(g_PTh + baseT);
        dst[0] = make_uint4(wds[0], wds[1], wds[2], wds[3]);
        dst[1] = make_uint4(wds[4], wds[5], wds[6], wds[7]);
        dst[2] = make_uint4(wds[8], wds[9], wds[10], wds[11]);
        dst[3] = make_uint4(wds[12], wds[13], wds[14], wds[15]);
    }

    // ---- Y = X@attW -> g_Yh, g_Ah = fp16(Y*s)
    PGEMM3(PW0_H);
    #pragma unroll
    for (int ni = 0; ni < 8; ni++) {
        int n = ni*8 + lanec;
        float s0 = *(const float*)(psm + PSC + n*4);
        float s1 = *(const float*)(psm + PSC + n*4 + 4);
        size_t gi0 = ((size_t)(row0 + m0l))*NF + n;
        size_t gi1 = ((size_t)(row0 + m0l + 8))*NF + n;
        *(uint32_t*)(g_Yh + gi0) = packh2(cacc[ni][0], cacc[ni][1]);
        *(uint32_t*)(g_Yh + gi1) = packh2(cacc[ni][2], cacc[ni][3]);
        *(uint32_t*)(g_Ah + gi0) = packh2(cacc[ni][0]*s0, cacc[ni][1]*s1);
        *(uint32_t*)(g_Ah + gi1) = packh2(cacc[ni][2]*s0, cacc[ni][3]*s1);
    }

    // ---- base = X@selfW + bias -> g_base (fp32)
    PGEMM3(PW2_H);
    #pragma unroll
    for (int ni = 0; ni < 8; ni++) {
        int n = ni*8 + lanec;
        float b0 = *(const float*)(psm + PBS + n*4);
        float b1 = *(const float*)(psm + PBS + n*4 + 4);
        size_t gi0 = ((size_t)(row0 + m0l))*NF + n;
        size_t gi1 = ((size_t)(row0 + m0l + 8))*NF + n;
        *(float2*)(g_base + gi0) = make_float2(cacc[ni][0] + b0, cacc[ni][1] + b1);
        *(float2*)(g_base + gi1) = make_float2(cacc[ni][2] + b0, cacc[ni][3] + b1);
    }
#undef PGEMM3
}

// ---------------------------------------------------------------------------
// Main kernel: 8 warps x (16 m-rows, full 64 n). GEMM1 1-term (A fp16 hoisted
// to registers), S passed GEMM1->GEMM2 in registers, B/P via cp.async double
// buffer. smem: A 16K | B x2 16K | P x2 16K = 48KB, occ 2.
#define SA_  0
#define SB0  16384
#define SB1  24576
#define SP0  32768
#define SP1  40960
#define SM_TOT 49152

__global__ void __launch_bounds__(256, 2)
main_kernel(float* __restrict__ out) {
    extern __shared__ char smem[];
    uint32_t sb = smem_u32(smem);
    int tid = threadIdx.x, wid = tid >> 5, lane = tid & 31;
    int bx = blockIdx.x, b = blockIdx.y;

    // Build A tile (fp16 of Yi*s) into swizzled smem
    {
        int r = tid >> 1, hf = tid & 1;
        const uint4* src = (const uint4*)(g_Ah + ((size_t)(b*NN + bx*128 + r))*NF + hf*32);
        uint32_t dst = sb + SA_ + swz_row((uint32_t)r * 128) ^ 0u;
        uint32_t base = sb + SA_ + swz_row((uint32_t)r * 128);
        #pragma unroll
        for (int j = 0; j < 4; j++)
            asm volatile("st.shared.v4.b32 [%0], {%1,%2,%3,%4};"
                         :: "r"(base ^ ((uint32_t)(hf*64 + j*16))),
                            "r"(src[j].x), "r"(src[j].y),
                            "r"(src[j].z), "r"(src[j].w) : "memory");
        (void)dst;
    }

    // cp.async tile kt=0 into SB0/SP0
    int tlr = tid >> 2, tsg = tid & 3;
    uint32_t ldst = swz_row((uint32_t)tlr*128) ^ ((uint32_t)tsg*32);
    {
        const char* yg = (const char*)(g_Yh + ((size_t)(b*NN + tlr))*NF + tsg*16);
        const char* pg = (const char*)(g_PTh + ((size_t)(b*NF + tlr))*NN + tsg*16);
        CPASYNC16(sb + SB0 + ldst,      yg);
        CPASYNC16(sb + SB0 + (ldst^16), yg + 16);
        CPASYNC16(sb + SP0 + ldst,      pg);
        CPASYNC16(sb + SP0 + (ldst^16), pg + 16);
        CPCOMMIT();
    }
    __syncthreads();   // A tile visible

    // Hoist A fragments (16 m-rows x 64 k) into registers: 16 regs
    uint32_t lr = lane & 15, lh = lane >> 4;
    uint32_t aRowB = swz_row((uint32_t)(wid*16 + lr)*128);
    uint32_t aH[4][4];
    #pragma unroll
    for (int kc = 0; kc < 4; kc++) {
        uint32_t axo = aRowB ^ ((uint32_t)(kc*32 + lh*16));
        LDSM4(aH[kc][0], aH[kc][1], aH[kc][2], aH[kc][3], sb + SA_ + axo);
    }

    uint32_t bRow[4];
    #pragma unroll
    for (int np = 0; np < 4; np++)
        bRow[np] = swz_row((uint32_t)(np*16 + lr)*128);

    float oacc[8][4];
    #pragma unroll
    for (int ni = 0; ni < 8; ni++)
        #pragma unroll
        for (int d = 0; d < 4; d++) oacc[ni][d] = 0.f;

    int lane4 = lane >> 2, lanec = (lane & 3) * 2;
    int m0 = bx*128 + wid*16 + lane4;
    const uint32_t bufB[2] = {SB0, SB1};
    const uint32_t bufP[2] = {SP0, SP1};

    for (int kt = 0; kt < 16; kt++) {
        int cur = kt & 1, nxt = cur ^ 1;

        CPWAIT0();
        __syncthreads();

        if (kt < 15) {
            const char* yg = (const char*)(g_Yh +
                ((size_t)(b*NN + (kt+1)*64 + tlr))*NF + tsg*16);
            const char* pg = (const char*)(g_PTh +
                ((size_t)(b*NF + tlr))*NN + (kt+1)*64 + tsg*16);
            CPASYNC16(sb + bufB[nxt] + ldst,      yg);
            CPASYNC16(sb + bufB[nxt] + (ldst^16), yg + 16);
            CPASYNC16(sb + bufP[nxt] + ldst,      pg);
            CPASYNC16(sb + bufP[nxt] + (ldst^16), pg + 16);
            CPCOMMIT();
        }

        // GEMM1: S = A @ Yk^T (1-term; A in registers)
        float sacc[8][4];
        #pragma unroll
        for (int ni = 0; ni < 8; ni++)
            #pragma unroll
            for (int d = 0; d < 4; d++) sacc[ni][d] = 0.f;
        #pragma unroll
        for (int kc = 0; kc < 4; kc++) {
            uint32_t colb = (uint32_t)(kc*32 + lh*16);
            uint32_t bh[8][2];
            #pragma unroll
            for (int np = 0; np < 4; np++) {
                uint32_t r0, r1, r2, r3;
                LDSM4(r0, r1, r2, r3, sb + bufB[cur] + (bRow[np] ^ colb));
                bh[np*2][0]=r0; bh[np*2][1]=r2;
                bh[np*2+1][0]=r1; bh[np*2+1][1]=r3;
            }
            #pragma unroll
            for (int ni = 0; ni < 8; ni++)
                mma16816(sacc[ni], aH[kc], bh[ni]);
        }

        // Register pass: leaky + diag-mask + pack C-frags into A-frags
        uint32_t aF[4][4];
        #pragma unroll
        for (int ni = 0; ni < 8; ni++) {
            int jg = kt*64 + ni*8 + lanec;
            float v0 = sacc[ni][0], v1 = sacc[ni][1];
            float v2 = sacc[ni][2], v3 = sacc[ni][3];
            v0 = (v0 > 0.f) ? v0 : 0.01f*v0;
            v1 = (v1 > 0.f) ? v1 : 0.01f*v1;
            v2 = (v2 > 0.f) ? v2 : 0.01f*v2;
            v3 = (v3 > 0.f) ? v3 : 0.01f*v3;
            if (m0     == jg)     v0 = 0.f;
            if (m0     == jg + 1) v1 = 0.f;
            if (m0 + 8 == jg)     v2 = 0.f;
            if (m0 + 8 == jg + 1) v3 = 0.f;
            aF[ni >> 1][(ni & 1)*2 + 0] = packh2(v0, v1);
            aF[ni >> 1][(ni & 1)*2 + 1] = packh2(v2, v3);
        }

        // GEMM2: O += S @ P
        #pragma unroll
        for (int kc = 0; kc < 4; kc++) {
            uint32_t colb = (uint32_t)(kc*32 + lh*16);
            uint32_t bh[8][2];
            #pragma unroll
            for (int np = 0; np < 4; np++) {
                uint32_t r0, r1, r2, r3;
                LDSM4(r0, r1, r2, r3, sb + bufP[cur] + (bRow[np] ^ colb));
                bh[np*2][0]=r0; bh[np*2][1]=r2;
                bh[np*2+1][0]=r1; bh[np*2+1][1]=r3;
            }
            #pragma unroll
            for (int ni = 0; ni < 8; ni++)
                mma16816(oacc[ni], aF[kc], bh[ni]);
        }
    }

    // Epilogue: out = O + base
    #pragma unroll
    for (int ni = 0; ni < 8; ni++) {
        int n = ni*8 + lanec;
        size_t gi0 = ((size_t)(b*NN + m0))*NF + n;
        size_t gi1 = ((size_t)(b*NN + m0 + 8))*NF + n;
        float2 b0 = *(const float2*)(g_base + gi0);
        float2 b1 = *(const float2*)(g_base + gi1);
        *(float2*)(out + gi0) = make_float2(oacc[ni][0] + b0.x, oacc[ni][1] + b0.y);
        *(float2*)(out + gi1) = make_float2(oacc[ni][2] + b1.x, oacc[ni][3] + b1.y);
    }
}

// ---------------------------------------------------------------------------
extern "C" void kernel_launch(void* const* d_in, const int* in_sizes, int n_in,
                              void* d_out, int out_size) {
    const float* X     = (const float*)d_in[0];
    // d_in[1] = A (unused in forward)
    const float* W     = (const float*)d_in[2];
    const float* attW  = (const float*)d_in[3];
    const float* amat  = (const float*)d_in[4];
    const float* bias  = (const float*)d_in[5];
    const float* selfW = (const float*)d_in[6];
    float* out = (float*)d_out;

    cudaFuncSetAttribute((const void*)prep_kernel,
                         cudaFuncAttributeMaxDynamicSharedMemorySize, PSM_TOT);
    cudaFuncSetAttribute((const void*)main_kernel,
                         cudaFuncAttributeMaxDynamicSharedMemorySize, SM_TOT);

    prep_kernel<<<NB*NN/128, 256, PSM_TOT>>>(X, W, attW, selfW, bias, amat);
    dim3 g2(NN/128, NB);
    main_kernel<<<g2, 256, SM_TOT>>>(out);
}